// round 13
// baseline (speedup 1.0000x reference)
#include <cuda_runtime.h>
#include <cuda_fp16.h>
#include <cstdint>

// Problem constants
#define NTOK   256
#define DH     64
#define NHEAD  8
#define CIN    512
#define NPROJ  2560   // 5*CIN
#define QI     4      // queries per attention CTA

// Scratch (device globals: no allocation allowed)
__device__ __align__(16) __half g_Ph[NTOK * NPROJ];     // projection, half
__device__ __align__(16) __half g_xh[NTOK * CIN],  g_xl[NTOK * CIN];
__device__ __align__(16) __half g_wah[CIN * NPROJ], g_wal[CIN * NPROJ];
__device__ __align__(16) __half g_woh[CIN * CIN],  g_wol[CIN * CIN];
__device__ __align__(16) __half g_yh[NTOK * CIN],  g_yl[NTOK * CIN];

// ---------------- PTX helpers ----------------
__device__ __forceinline__ uint32_t smem_u32(const void* p) {
    uint32_t r;
    asm("{ .reg .u64 t; cvta.to.shared.u64 t, %1; cvt.u32.u64 %0, t; }"
        : "=r"(r) : "l"(p));
    return r;
}
__device__ __forceinline__ void ldsm_x4(uint32_t* r, uint32_t addr) {
    asm volatile("ldmatrix.sync.aligned.m8n8.x4.shared.b16 {%0,%1,%2,%3}, [%4];"
                 : "=r"(r[0]), "=r"(r[1]), "=r"(r[2]), "=r"(r[3]) : "r"(addr));
}
__device__ __forceinline__ void ldsm_x4_t(uint32_t* r, uint32_t addr) {
    asm volatile("ldmatrix.sync.aligned.m8n8.x4.trans.shared.b16 {%0,%1,%2,%3}, [%4];"
                 : "=r"(r[0]), "=r"(r[1]), "=r"(r[2]), "=r"(r[3]) : "r"(addr));
}
__device__ __forceinline__ void mma_f16(float* d, const uint32_t* a, uint32_t b0, uint32_t b1) {
    asm volatile(
        "mma.sync.aligned.m16n8k16.row.col.f32.f16.f16.f32 "
        "{%0,%1,%2,%3}, {%4,%5,%6,%7}, {%8,%9}, {%0,%1,%2,%3};"
        : "+f"(d[0]), "+f"(d[1]), "+f"(d[2]), "+f"(d[3])
        : "r"(a[0]), "r"(a[1]), "r"(a[2]), "r"(a[3]), "r"(b0), "r"(b1));
}
__device__ __forceinline__ uint32_t ex2_f16x2(uint32_t a) {
    uint32_t d;
    asm("ex2.approx.f16x2 %0, %1;" : "=r"(d) : "r"(a));
    return d;
}
__device__ __forceinline__ uint32_t hmul2u(uint32_t a, uint32_t b) {
    uint32_t d;
    asm("mul.f16x2 %0, %1, %2;" : "=r"(d) : "r"(a), "r"(b));
    return d;
}

// ---------- fp32 -> (hi, lo) half split of x, W_att, W_out ----------
__global__ __launch_bounds__(256) void cvt_split(
    const float* __restrict__ x, const float* __restrict__ wa,
    const float* __restrict__ wo)
{
    const int NX = NTOK * CIN / 4, NA = CIN * NPROJ / 4, NO = CIN * CIN / 4;
    int idx = blockIdx.x * 256 + threadIdx.x;
    const float4* src; __half2* hi; __half2* lo;
    if (idx < NX)            { src = (const float4*)x;  hi = (__half2*)g_xh;  lo = (__half2*)g_xl; }
    else if (idx < NX + NA)  { idx -= NX;      src = (const float4*)wa; hi = (__half2*)g_wah; lo = (__half2*)g_wal; }
    else if (idx < NX+NA+NO) { idx -= NX + NA; src = (const float4*)wo; hi = (__half2*)g_woh; lo = (__half2*)g_wol; }
    else return;
    float4 v = src[idx];
    __half h0 = __float2half_rn(v.x), h1 = __float2half_rn(v.y);
    __half h2 = __float2half_rn(v.z), h3 = __float2half_rn(v.w);
    hi[idx * 2]     = __halves2half2(h0, h1);
    hi[idx * 2 + 1] = __halves2half2(h2, h3);
    lo[idx * 2]     = __halves2half2(__float2half_rn(v.x - __half2float(h0)),
                                     __float2half_rn(v.y - __half2float(h1)));
    lo[idx * 2 + 1] = __halves2half2(__float2half_rn(v.z - __half2float(h2)),
                                     __float2half_rn(v.w - __half2float(h3)));
}

// ---------- tensor-core GEMM, fp16 hi/lo split, 2-stage gmem pipeline ----------
__global__ __launch_bounds__(256) void gemm_tc(
    const __half* __restrict__ Ah, const __half* __restrict__ Al,
    const __half* __restrict__ Bh, const __half* __restrict__ Bl,
    const float* __restrict__ bias, float* __restrict__ C,
    __half* __restrict__ Ch, int M, int N, int K)
{
    __shared__ __half sA[2][64 * 64];
    __shared__ __half sB[2][64 * 64];
    const int t = threadIdx.x, w = t >> 5, lane = t & 31;
    const int wm = w >> 1, wn = w & 1;
    const int m0 = blockIdx.y * 64, n0 = blockIdx.x * 64;
    const int T = lane >> 3, rr = lane & 7;

    float acc[4][4];
#pragma unroll
    for (int nt = 0; nt < 4; ++nt)
#pragma unroll
        for (int r = 0; r < 4; ++r) acc[nt][r] = 0.f;

    const int arow = wm * 16 + (T & 1) * 8 + rr;
    const int asw = arow & 7;
    const int brow = (T & 1) * 8 + rr;

    // prologue loads for k0 = 0
    uint4 pAh[2], pAl[2], pBh[2], pBl[2];
#pragma unroll
    for (int l = 0; l < 2; ++l) {
        int idx = l * 256 + t, row = idx >> 3, c = idx & 7;
        size_t aoff = (size_t)(m0 + row) * K + c * 8;
        pAh[l] = *(const uint4*)(Ah + aoff);
        pAl[l] = *(const uint4*)(Al + aoff);
        size_t boff = (size_t)row * N + n0 + c * 8;
        pBh[l] = *(const uint4*)(Bh + boff);
        pBl[l] = *(const uint4*)(Bl + boff);
    }

    for (int k0 = 0; k0 < K; k0 += 64) {
#pragma unroll
        for (int l = 0; l < 2; ++l) {
            int idx = l * 256 + t, row = idx >> 3, c = idx & 7, sw = c ^ (row & 7);
            ((uint4*)sA[0])[row * 8 + sw] = pAh[l];
            ((uint4*)sA[1])[row * 8 + sw] = pAl[l];
            ((uint4*)sB[0])[row * 8 + sw] = pBh[l];
            ((uint4*)sB[1])[row * 8 + sw] = pBl[l];
        }
        __syncthreads();

        if (k0 + 64 < K) {   // prefetch next k-block (overlaps ldsm+mma below)
#pragma unroll
            for (int l = 0; l < 2; ++l) {
                int idx = l * 256 + t, row = idx >> 3, c = idx & 7;
                size_t aoff = (size_t)(m0 + row) * K + (k0 + 64) + c * 8;
                pAh[l] = *(const uint4*)(Ah + aoff);
                pAl[l] = *(const uint4*)(Al + aoff);
                size_t boff = (size_t)(k0 + 64 + row) * N + n0 + c * 8;
                pBh[l] = *(const uint4*)(Bh + boff);
                pBl[l] = *(const uint4*)(Bl + boff);
            }
        }

        const uint32_t sAh_b = smem_u32(sA[0]), sAl_b = smem_u32(sA[1]);
        const uint32_t sBh_b = smem_u32(sB[0]), sBl_b = smem_u32(sB[1]);
        uint32_t ah[4][4], al[4][4], bh[4][2][4], bl[4][2][4];
#pragma unroll
        for (int kt = 0; kt < 4; ++kt) {
            uint32_t ach = (uint32_t)(arow * 128 + (((kt * 2 + (T >> 1)) ^ asw) * 16));
            ldsm_x4(ah[kt], sAh_b + ach);
            ldsm_x4(al[kt], sAl_b + ach);
            uint32_t rb = (uint32_t)((kt * 16 + brow) * 128);
#pragma unroll
            for (int np = 0; np < 2; ++np) {
                uint32_t bch = (uint32_t)(((wn * 4 + np * 2 + (T >> 1)) ^ rr) * 16);
                ldsm_x4_t(bh[kt][np], sBh_b + rb + bch);
                ldsm_x4_t(bl[kt][np], sBl_b + rb + bch);
            }
        }
#pragma unroll
        for (int kt = 0; kt < 4; ++kt)
#pragma unroll
            for (int np = 0; np < 2; ++np)
#pragma unroll
                for (int sub = 0; sub < 2; ++sub) {
                    int nt = np * 2 + sub;
                    uint32_t b0h = bh[kt][np][sub * 2], b1h = bh[kt][np][sub * 2 + 1];
                    uint32_t b0l = bl[kt][np][sub * 2], b1l = bl[kt][np][sub * 2 + 1];
                    mma_f16(acc[nt], ah[kt], b0h, b1h);
                    mma_f16(acc[nt], ah[kt], b0l, b1l);
                    mma_f16(acc[nt], al[kt], b0h, b1h);
                }
        __syncthreads();
    }

#pragma unroll
    for (int nt = 0; nt < 4; ++nt)
#pragma unroll
        for (int r = 0; r < 4; ++r) {
            int row = m0 + wm * 16 + (lane >> 2) + (r >> 1) * 8;
            int col = n0 + wn * 32 + nt * 8 + (lane & 3) * 2 + (r & 1);
            float v = acc[nt][r] + bias[col];
            if (C)  C[(size_t)row * N + col] = v;
            if (Ch) Ch[(size_t)row * N + col] = __float2half_rn(v);
        }
}

// ---------- third-order attention via tensor cores ----------
// One CTA per (4-query block, head). 512 threads = 16 warps; warp w owns
// j-rows [16w, 16w+16). Tiles kj/kk/vk/vj staged once, 4 queries sequential.
// Per query: A-fragments = ldsm(kj) * q-frag (scale*log2e folded -> ex2 softmax).
// smem: kj[32K] kk[32K] vk[32K] vj[32K] q[4*64 half] ybuf[16*64 f32] lbuf[16 f32]
#define SMEM_ATTN (131072 + 512 + 4096 + 64)
#define ONES2 0x3C003C00u

__global__ __launch_bounds__(512, 1) void attn_mma()
{
    const int i0 = blockIdx.x * QI, h = blockIdx.y;
    const int t = threadIdx.x;
    const int w = t >> 5, lane = t & 31;

    extern __shared__ char smem[];
    __half* kjs = (__half*)(smem);
    __half* kks = (__half*)(smem + 32768);
    __half* vks = (__half*)(smem + 65536);
    __half* vjs = (__half*)(smem + 98304);
    __half* qsm = (__half*)(smem + 131072);          // [QI][64]
    float*  ybuf = (float*)(smem + 131584);          // [16][64]
    float*  lbuf = (float*)(smem + 135680);          // [16]

    const int base = h * 5 * DH;

    // ---- stage tiles (each 2048 uint4; 4 per thread) ----
#pragma unroll
    for (int l = 0; l < 4; ++l) {
        int idx = l * 512 + t;
        int row = idx >> 3, c = idx & 7;
        int sw = c ^ (row & 7);
        const __half* src = g_Ph + row * NPROJ + base;
        ((uint4*)kjs)[row * 8 + sw] = ((const uint4*)(src + 1 * DH))[c];
        ((uint4*)kks)[row * 8 + sw] = ((const uint4*)(src + 2 * DH))[c];
        ((uint4*)vks)[row * 8 + sw] = ((const uint4*)(src + 4 * DH))[c];
        ((uint4*)vjs)[row * 8 + c]  = ((const uint4*)(src + 3 * DH))[c];
    }
    // scaled q for all QI queries (scale * log2(e) folded so exp -> ex2)
    if (t < QI * DH) {
        int qi = t >> 6, d = t & 63;
        float qv = __half2float(g_Ph[(i0 + qi) * NPROJ + base + d]);
        qsm[t] = __float2half_rn(qv * 0.18033688011112042f);
    }
    __syncthreads();

    const int T = lane >> 3;
    const int rr = lane & 7;
    const int arow = w * 16 + (T & 1) * 8 + rr;
    const int asw = arow & 7;
    uint32_t achx[4], chunkx[4];
#pragma unroll
    for (int c4 = 0; c4 < 4; ++c4) {
        achx[c4]   = (uint32_t)(arow * 128 + (((c4 * 2 + (T >> 1)) ^ asw) * 16));
        chunkx[c4] = (uint32_t)((((c4 * 2 + (T >> 1)) ^ rr) & 7) * 16);
    }
    const uint32_t rowoff0 = (uint32_t)(((T & 1) * 8 + rr) * 128);
    const uint32_t kjs_b = smem_u32(kjs);
    const uint32_t kks_b = smem_u32(kks);
    const uint32_t vks_b = smem_u32(vks);
    const int kcol = (lane & 3) * 2;

#pragma unroll 1
    for (int qi = 0; qi < QI; ++qi) {
        // ---- per-query A-fragments: kjq = kj * q (half) ----
        uint32_t afr[4][4];
#pragma unroll
        for (int kt = 0; kt < 4; ++kt) {
            ldsm_x4(afr[kt], kjs_b + achx[kt]);
            uint32_t q0 = *(const uint32_t*)(qsm + qi * 64 + kt * 16 + kcol);
            uint32_t q8 = *(const uint32_t*)(qsm + qi * 64 + kt * 16 + 8 + kcol);
            afr[kt][0] = hmul2u(afr[kt][0], q0);
            afr[kt][1] = hmul2u(afr[kt][1], q0);
            afr[kt][2] = hmul2u(afr[kt][2], q8);
            afr[kt][3] = hmul2u(afr[kt][3], q8);
        }

        float macc[8][4];
#pragma unroll
        for (int dn = 0; dn < 8; ++dn)
#pragma unroll
            for (int r = 0; r < 4; ++r) macc[dn][r] = 0.f;
        float lacc[4] = {0.f, 0.f, 0.f, 0.f};

        uint32_t bbA[4][4], bbB[4][4];
#pragma unroll
        for (int kt = 0; kt < 4; ++kt) ldsm_x4(bbA[kt], kks_b + rowoff0 + chunkx[kt]);

#define ATTN_STEP(BB, NP, BBN) do {                                               \
        float s0[4] = {0.f,0.f,0.f,0.f}, s1[4] = {0.f,0.f,0.f,0.f};               \
        _Pragma("unroll")                                                         \
        for (int kt = 0; kt < 4; ++kt) {                                          \
            mma_f16(s0, afr[kt], BB[kt][0], BB[kt][2]);                           \
            mma_f16(s1, afr[kt], BB[kt][1], BB[kt][3]);                           \
        }                                                                         \
        if ((NP) + 1 < 16) {                                                      \
            uint32_t ro = rowoff0 + (uint32_t)(((NP) + 1) * 2048);                \
            _Pragma("unroll")                                                     \
            for (int kt = 0; kt < 4; ++kt) ldsm_x4(BBN[kt], kks_b + ro + chunkx[kt]); \
        }                                                                         \
        uint32_t pa[4];                                                           \
        { __half2 ph;                                                             \
          ph = __floats2half2_rn(s0[0], s0[1]); pa[0] = ex2_f16x2(*(uint32_t*)&ph); \
          ph = __floats2half2_rn(s0[2], s0[3]); pa[1] = ex2_f16x2(*(uint32_t*)&ph); \
          ph = __floats2half2_rn(s1[0], s1[1]); pa[2] = ex2_f16x2(*(uint32_t*)&ph); \
          ph = __floats2half2_rn(s1[2], s1[3]); pa[3] = ex2_f16x2(*(uint32_t*)&ph); } \
        uint32_t vb[4][4];                                                        \
        { uint32_t ro = rowoff0 + (uint32_t)((NP) * 2048);                        \
          _Pragma("unroll")                                                       \
          for (int dp = 0; dp < 4; ++dp) ldsm_x4_t(vb[dp], vks_b + ro + chunkx[dp]); } \
        _Pragma("unroll")                                                         \
        for (int dn = 0; dn < 8; ++dn) {                                          \
            int dp = dn >> 1;                                                     \
            if (dn & 1) mma_f16(macc[dn], pa, vb[dp][2], vb[dp][3]);              \
            else        mma_f16(macc[dn], pa, vb[dp][0], vb[dp][1]);              \
        }                                                                         \
        mma_f16(lacc, pa, ONES2, ONES2);                                          \
    } while (0)

#pragma unroll 1
        for (int np = 0; np < 16; np += 2) {
            ATTN_STEP(bbA, np, bbB);
            ATTN_STEP(bbB, np + 1, bbA);
        }
#undef ATTN_STEP

        // ---- denominator (each row sum replicated across 8 cols) ----
        float lsum = lacc[0] + lacc[1] + lacc[2] + lacc[3];
#pragma unroll
        for (int o = 16; o > 0; o >>= 1) lsum += __shfl_xor_sync(0xffffffffu, lsum, o);
        if (lane == 0) lbuf[w] = lsum * 0.125f;

        // ---- y partials: sum_j vj[j,d] * M[j,d] over this warp's 16 rows ----
        float ps[8][2];
#pragma unroll
        for (int nt = 0; nt < 8; ++nt) { ps[nt][0] = 0.f; ps[nt][1] = 0.f; }
#pragma unroll
        for (int nt = 0; nt < 8; ++nt) {
            int d0 = nt * 8 + (lane & 3) * 2;
#pragma unroll
            for (int rg = 0; rg < 2; ++rg) {
                int j = w * 16 + (lane >> 2) + rg * 8;
                float2 vf = __half22float2(*(const __half2*)(vjs + j * 64 + d0));
                ps[nt][0] += macc[nt][rg * 2]     * vf.x;
                ps[nt][1] += macc[nt][rg * 2 + 1] * vf.y;
            }
        }
#pragma unroll
        for (int o = 4; o <= 16; o <<= 1)
#pragma unroll
            for (int nt = 0; nt < 8; ++nt) {
                ps[nt][0] += __shfl_xor_sync(0xffffffffu, ps[nt][0], o);
                ps[nt][1] += __shfl_xor_sync(0xffffffffu, ps[nt][1], o);
            }
        if (lane < 4) {
#pragma unroll
            for (int nt = 0; nt < 8; ++nt) {
                ybuf[w * 64 + nt * 8 + lane * 2]     = ps[nt][0];
                ybuf[w * 64 + nt * 8 + lane * 2 + 1] = ps[nt][1];
            }
        }
        __syncthreads();

        if (t < DH) {
            float acc2 = 0.f, lt = 0.f;
#pragma unroll
            for (int ww = 0; ww < 16; ++ww) { acc2 += ybuf[ww * 64 + t]; lt += lbuf[ww]; }
            float y = acc2 / lt;
            __half hy = __float2half_rn(y);
            g_yh[(i0 + qi) * CIN + h * DH + t] = hy;
            g_yl[(i0 + qi) * CIN + h * DH + t] = __float2half_rn(y - __half2float(hy));
        }
        __syncthreads();   // ybuf/lbuf reused by next query
    }
}

// ---------------------------------------------------------------------------
extern "C" void kernel_launch(void* const* d_in, const int* in_sizes, int n_in,
                              void* d_out, int out_size)
{
    const float* x     = (const float*)d_in[0];
    const float* W_att = (const float*)d_in[1];
    const float* b_att = (const float*)d_in[2];
    const float* W_out = (const float*)d_in[3];
    const float* b_out = (const float*)d_in[4];
    float* out = (float*)d_out;

    void *pxh, *pxl, *pwah, *pwal, *pwoh, *pwol, *pPh, *pyh, *pyl;
    cudaGetSymbolAddress(&pxh, g_xh);   cudaGetSymbolAddress(&pxl, g_xl);
    cudaGetSymbolAddress(&pwah, g_wah); cudaGetSymbolAddress(&pwal, g_wal);
    cudaGetSymbolAddress(&pwoh, g_woh); cudaGetSymbolAddress(&pwol, g_wol);
    cudaGetSymbolAddress(&pPh, g_Ph);
    cudaGetSymbolAddress(&pyh, g_yh);   cudaGetSymbolAddress(&pyl, g_yl);

    // 0) split-convert inputs to (hi, lo) halves
    const int n4 = (NTOK * CIN + CIN * NPROJ + CIN * CIN) / 4;
    cvt_split<<<(n4 + 255) / 256, 256>>>(x, W_att, W_out);

    // 1) projection: g_Ph = half(x @ W_att + b_att), fp32-quality via 3-mma split
    gemm_tc<<<dim3(NPROJ / 64, NTOK / 64), 256>>>(
        (const __half*)pxh, (const __half*)pxl,
        (const __half*)pwah, (const __half*)pwal,
        b_att, nullptr, (__half*)pPh, NTOK, NPROJ, CIN);

    // 2) third-order attention (16 warps, 4 queries per CTA)
    cudaFuncSetAttribute(attn_mma, cudaFuncAttributeMaxDynamicSharedMemorySize, SMEM_ATTN);
    attn_mma<<<dim3(NTOK / QI, NHEAD), 512, SMEM_ATTN>>>();

    // 3) out projection: out = (Yh+Yl) @ (Woh+Wol) + b_out
    gemm_tc<<<dim3(CIN / 64, NTOK / 64), 256>>>(
        (const __half*)pyh, (const __half*)pyl,
        (const __half*)pwoh, (const __half*)pwol,
        b_out, out, nullptr, NTOK, CIN, CIN);
}

// round 14
// speedup vs baseline: 1.1436x; 1.1436x over previous
#include <cuda_runtime.h>
#include <cuda_fp16.h>
#include <cstdint>

// Problem constants
#define NTOK   256
#define DH     64
#define NHEAD  8
#define CIN    512
#define NPROJ  2560   // 5*CIN

// Scratch (device globals: no allocation allowed)
__device__ __align__(16) __half g_Ph[NTOK * NPROJ];     // projection, half
__device__ __align__(16) __half g_xh[NTOK * CIN],  g_xl[NTOK * CIN];
__device__ __align__(16) __half g_wah[CIN * NPROJ], g_wal[CIN * NPROJ];
__device__ __align__(16) __half g_woh[CIN * CIN],  g_wol[CIN * CIN];
__device__ __align__(16) __half g_yh[NTOK * CIN],  g_yl[NTOK * CIN];

// ---------------- PTX helpers ----------------
__device__ __forceinline__ uint32_t smem_u32(const void* p) {
    uint32_t r;
    asm("{ .reg .u64 t; cvta.to.shared.u64 t, %1; cvt.u32.u64 %0, t; }"
        : "=r"(r) : "l"(p));
    return r;
}
__device__ __forceinline__ void ldsm_x4(uint32_t* r, uint32_t addr) {
    asm volatile("ldmatrix.sync.aligned.m8n8.x4.shared.b16 {%0,%1,%2,%3}, [%4];"
                 : "=r"(r[0]), "=r"(r[1]), "=r"(r[2]), "=r"(r[3]) : "r"(addr));
}
__device__ __forceinline__ void ldsm_x4_t(uint32_t* r, uint32_t addr) {
    asm volatile("ldmatrix.sync.aligned.m8n8.x4.trans.shared.b16 {%0,%1,%2,%3}, [%4];"
                 : "=r"(r[0]), "=r"(r[1]), "=r"(r[2]), "=r"(r[3]) : "r"(addr));
}
__device__ __forceinline__ void mma_f16(float* d, const uint32_t* a, uint32_t b0, uint32_t b1) {
    asm volatile(
        "mma.sync.aligned.m16n8k16.row.col.f32.f16.f16.f32 "
        "{%0,%1,%2,%3}, {%4,%5,%6,%7}, {%8,%9}, {%0,%1,%2,%3};"
        : "+f"(d[0]), "+f"(d[1]), "+f"(d[2]), "+f"(d[3])
        : "r"(a[0]), "r"(a[1]), "r"(a[2]), "r"(a[3]), "r"(b0), "r"(b1));
}
__device__ __forceinline__ uint32_t ex2_f16x2(uint32_t a) {
    uint32_t d;
    asm("ex2.approx.f16x2 %0, %1;" : "=r"(d) : "r"(a));
    return d;
}
__device__ __forceinline__ uint32_t hmul2u(uint32_t a, uint32_t b) {
    uint32_t d;
    asm("mul.f16x2 %0, %1, %2;" : "=r"(d) : "r"(a), "r"(b));
    return d;
}

// ---------- fp32 -> (hi, lo) half split of x, W_att, W_out ----------
__global__ __launch_bounds__(256) void cvt_split(
    const float* __restrict__ x, const float* __restrict__ wa,
    const float* __restrict__ wo)
{
    const int NX = NTOK * CIN / 4, NA = CIN * NPROJ / 4, NO = CIN * CIN / 4;
    int idx = blockIdx.x * 256 + threadIdx.x;
    const float4* src; __half2* hi; __half2* lo;
    if (idx < NX)            { src = (const float4*)x;  hi = (__half2*)g_xh;  lo = (__half2*)g_xl; }
    else if (idx < NX + NA)  { idx -= NX;      src = (const float4*)wa; hi = (__half2*)g_wah; lo = (__half2*)g_wal; }
    else if (idx < NX+NA+NO) { idx -= NX + NA; src = (const float4*)wo; hi = (__half2*)g_woh; lo = (__half2*)g_wol; }
    else return;
    float4 v = src[idx];
    __half h0 = __float2half_rn(v.x), h1 = __float2half_rn(v.y);
    __half h2 = __float2half_rn(v.z), h3 = __float2half_rn(v.w);
    hi[idx * 2]     = __halves2half2(h0, h1);
    hi[idx * 2 + 1] = __halves2half2(h2, h3);
    lo[idx * 2]     = __halves2half2(__float2half_rn(v.x - __half2float(h0)),
                                     __float2half_rn(v.y - __half2float(h1)));
    lo[idx * 2 + 1] = __halves2half2(__float2half_rn(v.z - __half2float(h2)),
                                     __float2half_rn(v.w - __half2float(h3)));
}

// ---------- tensor-core GEMM, fp16 hi/lo split, 2-stage gmem pipeline ----------
__global__ __launch_bounds__(256) void gemm_tc(
    const __half* __restrict__ Ah, const __half* __restrict__ Al,
    const __half* __restrict__ Bh, const __half* __restrict__ Bl,
    const float* __restrict__ bias, float* __restrict__ C,
    __half* __restrict__ Ch, int M, int N, int K)
{
    __shared__ __half sA[2][64 * 64];
    __shared__ __half sB[2][64 * 64];
    const int t = threadIdx.x, w = t >> 5, lane = t & 31;
    const int wm = w >> 1, wn = w & 1;
    const int m0 = blockIdx.y * 64, n0 = blockIdx.x * 64;
    const int T = lane >> 3, rr = lane & 7;

    float acc[4][4];
#pragma unroll
    for (int nt = 0; nt < 4; ++nt)
#pragma unroll
        for (int r = 0; r < 4; ++r) acc[nt][r] = 0.f;

    const int arow = wm * 16 + (T & 1) * 8 + rr;
    const int asw = arow & 7;
    const int brow = (T & 1) * 8 + rr;

    uint4 pAh[2], pAl[2], pBh[2], pBl[2];
#pragma unroll
    for (int l = 0; l < 2; ++l) {
        int idx = l * 256 + t, row = idx >> 3, c = idx & 7;
        size_t aoff = (size_t)(m0 + row) * K + c * 8;
        pAh[l] = *(const uint4*)(Ah + aoff);
        pAl[l] = *(const uint4*)(Al + aoff);
        size_t boff = (size_t)row * N + n0 + c * 8;
        pBh[l] = *(const uint4*)(Bh + boff);
        pBl[l] = *(const uint4*)(Bl + boff);
    }

    for (int k0 = 0; k0 < K; k0 += 64) {
#pragma unroll
        for (int l = 0; l < 2; ++l) {
            int idx = l * 256 + t, row = idx >> 3, c = idx & 7, sw = c ^ (row & 7);
            ((uint4*)sA[0])[row * 8 + sw] = pAh[l];
            ((uint4*)sA[1])[row * 8 + sw] = pAl[l];
            ((uint4*)sB[0])[row * 8 + sw] = pBh[l];
            ((uint4*)sB[1])[row * 8 + sw] = pBl[l];
        }
        __syncthreads();

        if (k0 + 64 < K) {
#pragma unroll
            for (int l = 0; l < 2; ++l) {
                int idx = l * 256 + t, row = idx >> 3, c = idx & 7;
                size_t aoff = (size_t)(m0 + row) * K + (k0 + 64) + c * 8;
                pAh[l] = *(const uint4*)(Ah + aoff);
                pAl[l] = *(const uint4*)(Al + aoff);
                size_t boff = (size_t)(k0 + 64 + row) * N + n0 + c * 8;
                pBh[l] = *(const uint4*)(Bh + boff);
                pBl[l] = *(const uint4*)(Bl + boff);
            }
        }

        const uint32_t sAh_b = smem_u32(sA[0]), sAl_b = smem_u32(sA[1]);
        const uint32_t sBh_b = smem_u32(sB[0]), sBl_b = smem_u32(sB[1]);
        uint32_t ah[4][4], al[4][4], bh[4][2][4], bl[4][2][4];
#pragma unroll
        for (int kt = 0; kt < 4; ++kt) {
            uint32_t ach = (uint32_t)(arow * 128 + (((kt * 2 + (T >> 1)) ^ asw) * 16));
            ldsm_x4(ah[kt], sAh_b + ach);
            ldsm_x4(al[kt], sAl_b + ach);
            uint32_t rb = (uint32_t)((kt * 16 + brow) * 128);
#pragma unroll
            for (int np = 0; np < 2; ++np) {
                uint32_t bch = (uint32_t)(((wn * 4 + np * 2 + (T >> 1)) ^ rr) * 16);
                ldsm_x4_t(bh[kt][np], sBh_b + rb + bch);
                ldsm_x4_t(bl[kt][np], sBl_b + rb + bch);
            }
        }
#pragma unroll
        for (int kt = 0; kt < 4; ++kt)
#pragma unroll
            for (int np = 0; np < 2; ++np)
#pragma unroll
                for (int sub = 0; sub < 2; ++sub) {
                    int nt = np * 2 + sub;
                    uint32_t b0h = bh[kt][np][sub * 2], b1h = bh[kt][np][sub * 2 + 1];
                    uint32_t b0l = bl[kt][np][sub * 2], b1l = bl[kt][np][sub * 2 + 1];
                    mma_f16(acc[nt], ah[kt], b0h, b1h);
                    mma_f16(acc[nt], ah[kt], b0l, b1l);
                    mma_f16(acc[nt], al[kt], b0h, b1h);
                }
        __syncthreads();
    }

#pragma unroll
    for (int nt = 0; nt < 4; ++nt)
#pragma unroll
        for (int r = 0; r < 4; ++r) {
            int row = m0 + wm * 16 + (lane >> 2) + (r >> 1) * 8;
            int col = n0 + wn * 32 + nt * 8 + (lane & 3) * 2 + (r & 1);
            float v = acc[nt][r] + bias[col];
            if (C)  C[(size_t)row * N + col] = v;
            if (Ch) Ch[(size_t)row * N + col] = __float2half_rn(v);
        }
}

// ---------- third-order attention via tensor cores ----------
// One CTA per (query PAIR, head): 1024 CTAs, 256 threads (8 warps).
// Warps 0-3 handle query i0 (64 j-rows each: 4 m-tiles), warps 4-7 query i0+1.
// Each bb/vb fragment load is amortized over 4 m-tiles of mma (LDS/query = 256KB,
// half of R12, quarter of R13); per-warp ILP = 4 independent m-tile chains.
// ex2.f16x2 softmax in log2 domain; row sums via ones-column mma.
#define SMEM_ATTN 133408
#define ONES2 0x3C003C00u

__global__ __launch_bounds__(256, 1) void attn_mma()
{
    const int i0 = blockIdx.x * 2, h = blockIdx.y;
    const int t = threadIdx.x;
    const int w = t >> 5, lane = t & 31;
    const int qw = w >> 2;          // which query this warp serves
    const int ww = w & 3;           // warp index within query (owns 64 j-rows)

    extern __shared__ char smem[];
    __half* kjs = (__half*)(smem);
    __half* kks = (__half*)(smem + 32768);
    __half* vks = (__half*)(smem + 65536);
    __half* vjs = (__half*)(smem + 98304);
    __half* qsm = (__half*)(smem + 131072);          // [2][64]
    float*  ybuf = (float*)(smem + 131328);          // [8][64]
    float*  lbuf = (float*)(smem + 133376);          // [8]

    const int base = h * 5 * DH;

    // ---- stage tiles (each 2048 uint4; 8 per thread) ----
#pragma unroll
    for (int l = 0; l < 8; ++l) {
        int idx = l * 256 + t;
        int row = idx >> 3, c = idx & 7;
        int sw = c ^ (row & 7);
        const __half* src = g_Ph + row * NPROJ + base;
        ((uint4*)kjs)[row * 8 + sw] = ((const uint4*)(src + 1 * DH))[c];
        ((uint4*)kks)[row * 8 + sw] = ((const uint4*)(src + 2 * DH))[c];
        ((uint4*)vks)[row * 8 + sw] = ((const uint4*)(src + 4 * DH))[c];
        ((uint4*)vjs)[row * 8 + c]  = ((const uint4*)(src + 3 * DH))[c];
    }
    // scaled q for both queries (scale * log2(e) folded so exp -> ex2)
    if (t < 2 * DH) {
        int qi = t >> 6, d = t & 63;
        float qv = __half2float(g_Ph[(i0 + qi) * NPROJ + base + d]);
        qsm[t] = __float2half_rn(qv * 0.18033688011112042f);
    }
    __syncthreads();

    const int T = lane >> 3;
    const int rr = lane & 7;
    // row & 7 == rr for every fragment row here (all row bases are multiples of 8)
    uint32_t chunkx[4];
#pragma unroll
    for (int c4 = 0; c4 < 4; ++c4)
        chunkx[c4] = (uint32_t)((((c4 * 2 + (T >> 1)) ^ rr) & 7) * 16);
    const uint32_t rowoff0 = (uint32_t)(((T & 1) * 8 + rr) * 128);
    const uint32_t kks_b = smem_u32(kks);
    const uint32_t vks_b = smem_u32(vks);
    const int kcol = (lane & 3) * 2;

    // ---- A-fragments: afr[mt] = ldsm(kj rows) * q-frag, 4 m-tiles ----
    uint32_t afr[4][4][4];
    {
        const uint32_t kjs_b = smem_u32(kjs);
#pragma unroll
        for (int mt = 0; mt < 4; ++mt) {
            uint32_t rbase = (uint32_t)((ww * 64 + mt * 16) * 128) + rowoff0;
#pragma unroll
            for (int kt = 0; kt < 4; ++kt) {
                ldsm_x4(afr[mt][kt], kjs_b + rbase + chunkx[kt]);
                uint32_t q0 = *(const uint32_t*)(qsm + qw * 64 + kt * 16 + kcol);
                uint32_t q8 = *(const uint32_t*)(qsm + qw * 64 + kt * 16 + 8 + kcol);
                afr[mt][kt][0] = hmul2u(afr[mt][kt][0], q0);
                afr[mt][kt][1] = hmul2u(afr[mt][kt][1], q0);
                afr[mt][kt][2] = hmul2u(afr[mt][kt][2], q8);
                afr[mt][kt][3] = hmul2u(afr[mt][kt][3], q8);
            }
        }
    }

    float macc[4][8][4];
#pragma unroll
    for (int mt = 0; mt < 4; ++mt)
#pragma unroll
        for (int dn = 0; dn < 8; ++dn)
#pragma unroll
            for (int r = 0; r < 4; ++r) macc[mt][dn][r] = 0.f;
    float lacc[4] = {0.f, 0.f, 0.f, 0.f};

#pragma unroll 1
    for (int np = 0; np < 16; ++np) {
        const uint32_t ro = rowoff0 + (uint32_t)(np * 2048);
        uint32_t fr[4][4];                 // shared storage: bb then vb
#pragma unroll
        for (int kt = 0; kt < 4; ++kt) ldsm_x4(fr[kt], kks_b + ro + chunkx[kt]);

        // S = KJq @ KK^T per m-tile, exp via ex2.f16x2 -> pa fragments
        uint32_t pa[4][4];
#pragma unroll
        for (int mt = 0; mt < 4; ++mt) {
            float s0[4] = {0.f, 0.f, 0.f, 0.f}, s1[4] = {0.f, 0.f, 0.f, 0.f};
#pragma unroll
            for (int kt = 0; kt < 4; ++kt) {
                mma_f16(s0, afr[mt][kt], fr[kt][0], fr[kt][2]);
                mma_f16(s1, afr[mt][kt], fr[kt][1], fr[kt][3]);
            }
            __half2 ph;
            ph = __floats2half2_rn(s0[0], s0[1]); pa[mt][0] = ex2_f16x2(*(uint32_t*)&ph);
            ph = __floats2half2_rn(s0[2], s0[3]); pa[mt][1] = ex2_f16x2(*(uint32_t*)&ph);
            ph = __floats2half2_rn(s1[0], s1[1]); pa[mt][2] = ex2_f16x2(*(uint32_t*)&ph);
            ph = __floats2half2_rn(s1[2], s1[3]); pa[mt][3] = ex2_f16x2(*(uint32_t*)&ph);
        }

        // VK B-fragments (reuse fr storage; WAR on fr orders after the S mmas)
#pragma unroll
        for (int dp = 0; dp < 4; ++dp) ldsm_x4_t(fr[dp], vks_b + ro + chunkx[dp]);

        // M += P @ VK per m-tile; lsum via ones-column mma
#pragma unroll
        for (int mt = 0; mt < 4; ++mt) {
#pragma unroll
            for (int dn = 0; dn < 8; ++dn) {
                int dp = dn >> 1;
                if (dn & 1) mma_f16(macc[mt][dn], pa[mt], fr[dp][2], fr[dp][3]);
                else        mma_f16(macc[mt][dn], pa[mt], fr[dp][0], fr[dp][1]);
            }
            mma_f16(lacc, pa[mt], ONES2, ONES2);
        }
    }

    // ---- denominator (each row sum replicated across 8 lanes/cols) ----
    float lsum = lacc[0] + lacc[1] + lacc[2] + lacc[3];
#pragma unroll
    for (int o = 16; o > 0; o >>= 1) lsum += __shfl_xor_sync(0xffffffffu, lsum, o);
    if (lane == 0) lbuf[w] = lsum * 0.125f;

    // ---- y partials: sum_j vj[j,d] * M[j,d] over this warp's 64 rows ----
    float ps[8][2];
#pragma unroll
    for (int nt = 0; nt < 8; ++nt) { ps[nt][0] = 0.f; ps[nt][1] = 0.f; }
#pragma unroll
    for (int mt = 0; mt < 4; ++mt)
#pragma unroll
        for (int nt = 0; nt < 8; ++nt) {
            int d0 = nt * 8 + (lane & 3) * 2;
#pragma unroll
            for (int rg = 0; rg < 2; ++rg) {
                int j = ww * 64 + mt * 16 + (lane >> 2) + rg * 8;
                float2 vf = __half22float2(*(const __half2*)(vjs + j * 64 + d0));
                ps[nt][0] += macc[mt][nt][rg * 2]     * vf.x;
                ps[nt][1] += macc[mt][nt][rg * 2 + 1] * vf.y;
            }
        }
#pragma unroll
    for (int o = 4; o <= 16; o <<= 1)
#pragma unroll
        for (int nt = 0; nt < 8; ++nt) {
            ps[nt][0] += __shfl_xor_sync(0xffffffffu, ps[nt][0], o);
            ps[nt][1] += __shfl_xor_sync(0xffffffffu, ps[nt][1], o);
        }
    if (lane < 4) {
#pragma unroll
        for (int nt = 0; nt < 8; ++nt) {
            ybuf[w * 64 + nt * 8 + lane * 2]     = ps[nt][0];
            ybuf[w * 64 + nt * 8 + lane * 2 + 1] = ps[nt][1];
        }
    }
    __syncthreads();

    // ---- finalize both queries: threads [0,64) -> q0, [64,128) -> q1 ----
    if (t < 2 * DH) {
        int qi = t >> 6, d = t & 63;
        float acc2 = 0.f, lt = 0.f;
#pragma unroll
        for (int ww2 = 0; ww2 < 4; ++ww2) {
            acc2 += ybuf[(qi * 4 + ww2) * 64 + d];
            lt   += lbuf[qi * 4 + ww2];
        }
        float y = acc2 / lt;
        __half hy = __float2half_rn(y);
        g_yh[(i0 + qi) * CIN + h * DH + d] = hy;
        g_yl[(i0 + qi) * CIN + h * DH + d] = __float2half_rn(y - __half2float(hy));
    }
}

// ---------------------------------------------------------------------------
extern "C" void kernel_launch(void* const* d_in, const int* in_sizes, int n_in,
                              void* d_out, int out_size)
{
    const float* x     = (const float*)d_in[0];
    const float* W_att = (const float*)d_in[1];
    const float* b_att = (const float*)d_in[2];
    const float* W_out = (const float*)d_in[3];
    const float* b_out = (const float*)d_in[4];
    float* out = (float*)d_out;

    void *pxh, *pxl, *pwah, *pwal, *pwoh, *pwol, *pPh, *pyh, *pyl;
    cudaGetSymbolAddress(&pxh, g_xh);   cudaGetSymbolAddress(&pxl, g_xl);
    cudaGetSymbolAddress(&pwah, g_wah); cudaGetSymbolAddress(&pwal, g_wal);
    cudaGetSymbolAddress(&pwoh, g_woh); cudaGetSymbolAddress(&pwol, g_wol);
    cudaGetSymbolAddress(&pPh, g_Ph);
    cudaGetSymbolAddress(&pyh, g_yh);   cudaGetSymbolAddress(&pyl, g_yl);

    // 0) split-convert inputs to (hi, lo) halves
    const int n4 = (NTOK * CIN + CIN * NPROJ + CIN * CIN) / 4;
    cvt_split<<<(n4 + 255) / 256, 256>>>(x, W_att, W_out);

    // 1) projection: g_Ph = half(x @ W_att + b_att), fp32-quality via 3-mma split
    gemm_tc<<<dim3(NPROJ / 64, NTOK / 64), 256>>>(
        (const __half*)pxh, (const __half*)pxl,
        (const __half*)pwah, (const __half*)pwal,
        b_att, nullptr, (__half*)pPh, NTOK, NPROJ, CIN);

    // 2) third-order attention (8 warps, query pair per CTA, 4 m-tiles/warp)
    cudaFuncSetAttribute(attn_mma, cudaFuncAttributeMaxDynamicSharedMemorySize, SMEM_ATTN);
    attn_mma<<<dim3(NTOK / 2, NHEAD), 256, SMEM_ATTN>>>();

    // 3) out projection: out = (Yh+Yl) @ (Woh+Wol) + b_out
    gemm_tc<<<dim3(CIN / 64, NTOK / 64), 256>>>(
        (const __half*)pyh, (const __half*)pyl,
        (const __half*)pwoh, (const __half*)pwol,
        b_out, out, nullptr, NTOK, CIN, CIN);
}

// round 15
// speedup vs baseline: 1.1789x; 1.0308x over previous
#include <cuda_runtime.h>
#include <cuda_fp16.h>
#include <cstdint>

// Problem constants
#define NTOK   256
#define DH     64
#define NHEAD  8
#define CIN    512
#define NPROJ  2560   // 5*CIN

// Scratch (device globals: no allocation allowed)
__device__ __align__(16) __half g_Ph[NTOK * NPROJ];     // projection, half
__device__ __align__(16) __half g_xh[NTOK * CIN],  g_xl[NTOK * CIN];
__device__ __align__(16) __half g_wah[CIN * NPROJ], g_wal[CIN * NPROJ];
__device__ __align__(16) __half g_woh[CIN * CIN],  g_wol[CIN * CIN];
__device__ __align__(16) __half g_yh[NTOK * CIN],  g_yl[NTOK * CIN];

// ---------------- PTX helpers ----------------
__device__ __forceinline__ uint32_t smem_u32(const void* p) {
    uint32_t r;
    asm("{ .reg .u64 t; cvta.to.shared.u64 t, %1; cvt.u32.u64 %0, t; }"
        : "=r"(r) : "l"(p));
    return r;
}
__device__ __forceinline__ void ldsm_x4(uint32_t* r, uint32_t addr) {
    asm volatile("ldmatrix.sync.aligned.m8n8.x4.shared.b16 {%0,%1,%2,%3}, [%4];"
                 : "=r"(r[0]), "=r"(r[1]), "=r"(r[2]), "=r"(r[3]) : "r"(addr));
}
__device__ __forceinline__ void ldsm_x4_t(uint32_t* r, uint32_t addr) {
    asm volatile("ldmatrix.sync.aligned.m8n8.x4.trans.shared.b16 {%0,%1,%2,%3}, [%4];"
                 : "=r"(r[0]), "=r"(r[1]), "=r"(r[2]), "=r"(r[3]) : "r"(addr));
}
// fp32-accumulator mma (PV, lsum, GEMMs)
__device__ __forceinline__ void mma_f16(float* d, const uint32_t* a, uint32_t b0, uint32_t b1) {
    asm volatile(
        "mma.sync.aligned.m16n8k16.row.col.f32.f16.f16.f32 "
        "{%0,%1,%2,%3}, {%4,%5,%6,%7}, {%8,%9}, {%0,%1,%2,%3};"
        : "+f"(d[0]), "+f"(d[1]), "+f"(d[2]), "+f"(d[3])
        : "r"(a[0]), "r"(a[1]), "r"(a[2]), "r"(a[3]), "r"(b0), "r"(b1));
}
// fp16-accumulator mma (scores): D regs are packed half2 {c0,c1},{c2,c3}
__device__ __forceinline__ void mma_f16acc(uint32_t* d, const uint32_t* a, uint32_t b0, uint32_t b1) {
    asm volatile(
        "mma.sync.aligned.m16n8k16.row.col.f16.f16.f16.f16 "
        "{%0,%1}, {%2,%3,%4,%5}, {%6,%7}, {%0,%1};"
        : "+r"(d[0]), "+r"(d[1])
        : "r"(a[0]), "r"(a[1]), "r"(a[2]), "r"(a[3]), "r"(b0), "r"(b1));
}
__device__ __forceinline__ uint32_t ex2_f16x2(uint32_t a) {
    uint32_t d;
    asm("ex2.approx.f16x2 %0, %1;" : "=r"(d) : "r"(a));
    return d;
}
__device__ __forceinline__ uint32_t hmul2u(uint32_t a, uint32_t b) {
    uint32_t d;
    asm("mul.f16x2 %0, %1, %2;" : "=r"(d) : "r"(a), "r"(b));
    return d;
}

// ---------- fp32 -> (hi, lo) half split of x, W_att, W_out ----------
__global__ __launch_bounds__(256) void cvt_split(
    const float* __restrict__ x, const float* __restrict__ wa,
    const float* __restrict__ wo)
{
    const int NX = NTOK * CIN / 4, NA = CIN * NPROJ / 4, NO = CIN * CIN / 4;
    int idx = blockIdx.x * 256 + threadIdx.x;
    const float4* src; __half2* hi; __half2* lo;
    if (idx < NX)            { src = (const float4*)x;  hi = (__half2*)g_xh;  lo = (__half2*)g_xl; }
    else if (idx < NX + NA)  { idx -= NX;      src = (const float4*)wa; hi = (__half2*)g_wah; lo = (__half2*)g_wal; }
    else if (idx < NX+NA+NO) { idx -= NX + NA; src = (const float4*)wo; hi = (__half2*)g_woh; lo = (__half2*)g_wol; }
    else return;
    float4 v = src[idx];
    __half h0 = __float2half_rn(v.x), h1 = __float2half_rn(v.y);
    __half h2 = __float2half_rn(v.z), h3 = __float2half_rn(v.w);
    hi[idx * 2]     = __halves2half2(h0, h1);
    hi[idx * 2 + 1] = __halves2half2(h2, h3);
    lo[idx * 2]     = __halves2half2(__float2half_rn(v.x - __half2float(h0)),
                                     __float2half_rn(v.y - __half2float(h1)));
    lo[idx * 2 + 1] = __halves2half2(__float2half_rn(v.z - __half2float(h2)),
                                     __float2half_rn(v.w - __half2float(h3)));
}

// ---------- tensor-core GEMM, fp16 hi/lo split, 2-stage gmem pipeline ----------
__global__ __launch_bounds__(256) void gemm_tc(
    const __half* __restrict__ Ah, const __half* __restrict__ Al,
    const __half* __restrict__ Bh, const __half* __restrict__ Bl,
    const float* __restrict__ bias, float* __restrict__ C,
    __half* __restrict__ Ch, int M, int N, int K)
{
    __shared__ __half sA[2][64 * 64];
    __shared__ __half sB[2][64 * 64];
    const int t = threadIdx.x, w = t >> 5, lane = t & 31;
    const int wm = w >> 1, wn = w & 1;
    const int m0 = blockIdx.y * 64, n0 = blockIdx.x * 64;
    const int T = lane >> 3, rr = lane & 7;

    float acc[4][4];
#pragma unroll
    for (int nt = 0; nt < 4; ++nt)
#pragma unroll
        for (int r = 0; r < 4; ++r) acc[nt][r] = 0.f;

    const int arow = wm * 16 + (T & 1) * 8 + rr;
    const int asw = arow & 7;
    const int brow = (T & 1) * 8 + rr;

    uint4 pAh[2], pAl[2], pBh[2], pBl[2];
#pragma unroll
    for (int l = 0; l < 2; ++l) {
        int idx = l * 256 + t, row = idx >> 3, c = idx & 7;
        size_t aoff = (size_t)(m0 + row) * K + c * 8;
        pAh[l] = *(const uint4*)(Ah + aoff);
        pAl[l] = *(const uint4*)(Al + aoff);
        size_t boff = (size_t)row * N + n0 + c * 8;
        pBh[l] = *(const uint4*)(Bh + boff);
        pBl[l] = *(const uint4*)(Bl + boff);
    }

    for (int k0 = 0; k0 < K; k0 += 64) {
#pragma unroll
        for (int l = 0; l < 2; ++l) {
            int idx = l * 256 + t, row = idx >> 3, c = idx & 7, sw = c ^ (row & 7);
            ((uint4*)sA[0])[row * 8 + sw] = pAh[l];
            ((uint4*)sA[1])[row * 8 + sw] = pAl[l];
            ((uint4*)sB[0])[row * 8 + sw] = pBh[l];
            ((uint4*)sB[1])[row * 8 + sw] = pBl[l];
        }
        __syncthreads();

        if (k0 + 64 < K) {
#pragma unroll
            for (int l = 0; l < 2; ++l) {
                int idx = l * 256 + t, row = idx >> 3, c = idx & 7;
                size_t aoff = (size_t)(m0 + row) * K + (k0 + 64) + c * 8;
                pAh[l] = *(const uint4*)(Ah + aoff);
                pAl[l] = *(const uint4*)(Al + aoff);
                size_t boff = (size_t)(k0 + 64 + row) * N + n0 + c * 8;
                pBh[l] = *(const uint4*)(Bh + boff);
                pBl[l] = *(const uint4*)(Bl + boff);
            }
        }

        const uint32_t sAh_b = smem_u32(sA[0]), sAl_b = smem_u32(sA[1]);
        const uint32_t sBh_b = smem_u32(sB[0]), sBl_b = smem_u32(sB[1]);
        uint32_t ah[4][4], al[4][4], bh[4][2][4], bl[4][2][4];
#pragma unroll
        for (int kt = 0; kt < 4; ++kt) {
            uint32_t ach = (uint32_t)(arow * 128 + (((kt * 2 + (T >> 1)) ^ asw) * 16));
            ldsm_x4(ah[kt], sAh_b + ach);
            ldsm_x4(al[kt], sAl_b + ach);
            uint32_t rb = (uint32_t)((kt * 16 + brow) * 128);
#pragma unroll
            for (int np = 0; np < 2; ++np) {
                uint32_t bch = (uint32_t)(((wn * 4 + np * 2 + (T >> 1)) ^ rr) * 16);
                ldsm_x4_t(bh[kt][np], sBh_b + rb + bch);
                ldsm_x4_t(bl[kt][np], sBl_b + rb + bch);
            }
        }
#pragma unroll
        for (int kt = 0; kt < 4; ++kt)
#pragma unroll
            for (int np = 0; np < 2; ++np)
#pragma unroll
                for (int sub = 0; sub < 2; ++sub) {
                    int nt = np * 2 + sub;
                    uint32_t b0h = bh[kt][np][sub * 2], b1h = bh[kt][np][sub * 2 + 1];
                    uint32_t b0l = bl[kt][np][sub * 2], b1l = bl[kt][np][sub * 2 + 1];
                    mma_f16(acc[nt], ah[kt], b0h, b1h);
                    mma_f16(acc[nt], ah[kt], b0l, b1l);
                    mma_f16(acc[nt], al[kt], b0h, b1h);
                }
        __syncthreads();
    }

#pragma unroll
    for (int nt = 0; nt < 4; ++nt)
#pragma unroll
        for (int r = 0; r < 4; ++r) {
            int row = m0 + wm * 16 + (lane >> 2) + (r >> 1) * 8;
            int col = n0 + wn * 32 + nt * 8 + (lane & 3) * 2 + (r & 1);
            float v = acc[nt][r] + bias[col];
            if (C)  C[(size_t)row * N + col] = v;
            if (Ch) Ch[(size_t)row * N + col] = __float2half_rn(v);
        }
}

// ---------- third-order attention via tensor cores ----------
// One CTA per (query PAIR, head): 1024 CTAs, 256 threads (8 warps).
// Warps 0-3 handle query i0 (64 j-rows each: 4 m-tiles), warps 4-7 query i0+1.
// S-mma uses an fp16 accumulator: result regs are packed half2 in exactly the
// ex2/A-fragment layout, so exp is mma -> ex2.f16x2 -> mma with no F2FP repack.
// bb and vb live in separate buffers, both loaded at the top of each np so the
// vb LDS latency hides under the S mmas instead of trailing them (no WAR chain).
#define SMEM_ATTN 133408
#define ONES2 0x3C003C00u

__global__ __launch_bounds__(256, 1) void attn_mma()
{
    const int i0 = blockIdx.x * 2, h = blockIdx.y;
    const int t = threadIdx.x;
    const int w = t >> 5, lane = t & 31;
    const int qw = w >> 2;          // which query this warp serves
    const int ww = w & 3;           // warp index within query (owns 64 j-rows)

    extern __shared__ char smem[];
    __half* kjs = (__half*)(smem);
    __half* kks = (__half*)(smem + 32768);
    __half* vks = (__half*)(smem + 65536);
    __half* vjs = (__half*)(smem + 98304);
    __half* qsm = (__half*)(smem + 131072);          // [2][64]
    float*  ybuf = (float*)(smem + 131328);          // [8][64]
    float*  lbuf = (float*)(smem + 133376);          // [8]

    const int base = h * 5 * DH;

    // ---- stage tiles (each 2048 uint4; 8 per thread) ----
#pragma unroll
    for (int l = 0; l < 8; ++l) {
        int idx = l * 256 + t;
        int row = idx >> 3, c = idx & 7;
        int sw = c ^ (row & 7);
        const __half* src = g_Ph + row * NPROJ + base;
        ((uint4*)kjs)[row * 8 + sw] = ((const uint4*)(src + 1 * DH))[c];
        ((uint4*)kks)[row * 8 + sw] = ((const uint4*)(src + 2 * DH))[c];
        ((uint4*)vks)[row * 8 + sw] = ((const uint4*)(src + 4 * DH))[c];
        ((uint4*)vjs)[row * 8 + c]  = ((const uint4*)(src + 3 * DH))[c];
    }
    // scaled q for both queries (scale * log2(e) folded so exp -> ex2)
    if (t < 2 * DH) {
        int qi = t >> 6, d = t & 63;
        float qv = __half2float(g_Ph[(i0 + qi) * NPROJ + base + d]);
        qsm[t] = __float2half_rn(qv * 0.18033688011112042f);
    }
    __syncthreads();

    const int T = lane >> 3;
    const int rr = lane & 7;
    uint32_t chunkx[4];
#pragma unroll
    for (int c4 = 0; c4 < 4; ++c4)
        chunkx[c4] = (uint32_t)((((c4 * 2 + (T >> 1)) ^ rr) & 7) * 16);
    const uint32_t rowoff0 = (uint32_t)(((T & 1) * 8 + rr) * 128);
    const uint32_t kks_b = smem_u32(kks);
    const uint32_t vks_b = smem_u32(vks);
    const int kcol = (lane & 3) * 2;

    // ---- A-fragments: afr[mt] = ldsm(kj rows) * q-frag, 4 m-tiles ----
    uint32_t afr[4][4][4];
    {
        const uint32_t kjs_b = smem_u32(kjs);
#pragma unroll
        for (int mt = 0; mt < 4; ++mt) {
            uint32_t rbase = (uint32_t)((ww * 64 + mt * 16) * 128) + rowoff0;
#pragma unroll
            for (int kt = 0; kt < 4; ++kt) {
                ldsm_x4(afr[mt][kt], kjs_b + rbase + chunkx[kt]);
                uint32_t q0 = *(const uint32_t*)(qsm + qw * 64 + kt * 16 + kcol);
                uint32_t q8 = *(const uint32_t*)(qsm + qw * 64 + kt * 16 + 8 + kcol);
                afr[mt][kt][0] = hmul2u(afr[mt][kt][0], q0);
                afr[mt][kt][1] = hmul2u(afr[mt][kt][1], q0);
                afr[mt][kt][2] = hmul2u(afr[mt][kt][2], q8);
                afr[mt][kt][3] = hmul2u(afr[mt][kt][3], q8);
            }
        }
    }

    float macc[4][8][4];
#pragma unroll
    for (int mt = 0; mt < 4; ++mt)
#pragma unroll
        for (int dn = 0; dn < 8; ++dn)
#pragma unroll
            for (int r = 0; r < 4; ++r) macc[mt][dn][r] = 0.f;
    float lacc[4] = {0.f, 0.f, 0.f, 0.f};

#pragma unroll 1
    for (int np = 0; np < 16; ++np) {
        const uint32_t ro = rowoff0 + (uint32_t)(np * 2048);
        uint32_t bb[4][4], vb[4][4];
        // Load BOTH fragment sets up front: vb's latency hides under S mmas/ex2.
#pragma unroll
        for (int kt = 0; kt < 4; ++kt) ldsm_x4(bb[kt], kks_b + ro + chunkx[kt]);
#pragma unroll
        for (int dp = 0; dp < 4; ++dp) ldsm_x4_t(vb[dp], vks_b + ro + chunkx[dp]);

        // S = KJq @ KK^T (fp16 acc, packed half2) -> exp via ex2.f16x2, no repack
        uint32_t pa[4][4];
#pragma unroll
        for (int mt = 0; mt < 4; ++mt) {
            uint32_t s0[2] = {0u, 0u}, s1[2] = {0u, 0u};   // nt0, nt1 half2 accums
#pragma unroll
            for (int kt = 0; kt < 4; ++kt) {
                mma_f16acc(s0, afr[mt][kt], bb[kt][0], bb[kt][2]);
                mma_f16acc(s1, afr[mt][kt], bb[kt][1], bb[kt][3]);
            }
            pa[mt][0] = ex2_f16x2(s0[0]);
            pa[mt][1] = ex2_f16x2(s0[1]);
            pa[mt][2] = ex2_f16x2(s1[0]);
            pa[mt][3] = ex2_f16x2(s1[1]);
        }

        // M += P @ VK per m-tile; lsum via ones-column mma (fp32 acc)
#pragma unroll
        for (int mt = 0; mt < 4; ++mt) {
#pragma unroll
            for (int dn = 0; dn < 8; ++dn) {
                int dp = dn >> 1;
                if (dn & 1) mma_f16(macc[mt][dn], pa[mt], vb[dp][2], vb[dp][3]);
                else        mma_f16(macc[mt][dn], pa[mt], vb[dp][0], vb[dp][1]);
            }
            mma_f16(lacc, pa[mt], ONES2, ONES2);
        }
    }

    // ---- denominator (each row sum replicated across 8 lanes/cols) ----
    float lsum = lacc[0] + lacc[1] + lacc[2] + lacc[3];
#pragma unroll
    for (int o = 16; o > 0; o >>= 1) lsum += __shfl_xor_sync(0xffffffffu, lsum, o);
    if (lane == 0) lbuf[w] = lsum * 0.125f;

    // ---- y partials: sum_j vj[j,d] * M[j,d] over this warp's 64 rows ----
    float ps[8][2];
#pragma unroll
    for (int nt = 0; nt < 8; ++nt) { ps[nt][0] = 0.f; ps[nt][1] = 0.f; }
#pragma unroll
    for (int mt = 0; mt < 4; ++mt)
#pragma unroll
        for (int nt = 0; nt < 8; ++nt) {
            int d0 = nt * 8 + (lane & 3) * 2;
#pragma unroll
            for (int rg = 0; rg < 2; ++rg) {
                int j = ww * 64 + mt * 16 + (lane >> 2) + rg * 8;
                float2 vf = __half22float2(*(const __half2*)(vjs + j * 64 + d0));
                ps[nt][0] += macc[mt][nt][rg * 2]     * vf.x;
                ps[nt][1] += macc[mt][nt][rg * 2 + 1] * vf.y;
            }
        }
#pragma unroll
    for (int o = 4; o <= 16; o <<= 1)
#pragma unroll
        for (int nt = 0; nt < 8; ++nt) {
            ps[nt][0] += __shfl_xor_sync(0xffffffffu, ps[nt][0], o);
            ps[nt][1] += __shfl_xor_sync(0xffffffffu, ps[nt][1], o);
        }
    if (lane < 4) {
#pragma unroll
        for (int nt = 0; nt < 8; ++nt) {
            ybuf[w * 64 + nt * 8 + lane * 2]     = ps[nt][0];
            ybuf[w * 64 + nt * 8 + lane * 2 + 1] = ps[nt][1];
        }
    }
    __syncthreads();

    // ---- finalize both queries: threads [0,64) -> q0, [64,128) -> q1 ----
    if (t < 2 * DH) {
        int qi = t >> 6, d = t & 63;
        float acc2 = 0.f, lt = 0.f;
#pragma unroll
        for (int ww2 = 0; ww2 < 4; ++ww2) {
            acc2 += ybuf[(qi * 4 + ww2) * 64 + d];
            lt   += lbuf[qi * 4 + ww2];
        }
        float y = acc2 / lt;
        __half hy = __float2half_rn(y);
        g_yh[(i0 + qi) * CIN + h * DH + d] = hy;
        g_yl[(i0 + qi) * CIN + h * DH + d] = __float2half_rn(y - __half2float(hy));
    }
}

// ---------------------------------------------------------------------------
extern "C" void kernel_launch(void* const* d_in, const int* in_sizes, int n_in,
                              void* d_out, int out_size)
{
    const float* x     = (const float*)d_in[0];
    const float* W_att = (const float*)d_in[1];
    const float* b_att = (const float*)d_in[2];
    const float* W_out = (const float*)d_in[3];
    const float* b_out = (const float*)d_in[4];
    float* out = (float*)d_out;

    void *pxh, *pxl, *pwah, *pwal, *pwoh, *pwol, *pPh, *pyh, *pyl;
    cudaGetSymbolAddress(&pxh, g_xh);   cudaGetSymbolAddress(&pxl, g_xl);
    cudaGetSymbolAddress(&pwah, g_wah); cudaGetSymbolAddress(&pwal, g_wal);
    cudaGetSymbolAddress(&pwoh, g_woh); cudaGetSymbolAddress(&pwol, g_wol);
    cudaGetSymbolAddress(&pPh, g_Ph);
    cudaGetSymbolAddress(&pyh, g_yh);   cudaGetSymbolAddress(&pyl, g_yl);

    // 0) split-convert inputs to (hi, lo) halves
    const int n4 = (NTOK * CIN + CIN * NPROJ + CIN * CIN) / 4;
    cvt_split<<<(n4 + 255) / 256, 256>>>(x, W_att, W_out);

    // 1) projection: g_Ph = half(x @ W_att + b_att), fp32-quality via 3-mma split
    gemm_tc<<<dim3(NPROJ / 64, NTOK / 64), 256>>>(
        (const __half*)pxh, (const __half*)pxl,
        (const __half*)pwah, (const __half*)pwal,
        b_att, nullptr, (__half*)pPh, NTOK, NPROJ, CIN);

    // 2) third-order attention (8 warps, query pair per CTA, f16-acc scores)
    cudaFuncSetAttribute(attn_mma, cudaFuncAttributeMaxDynamicSharedMemorySize, SMEM_ATTN);
    attn_mma<<<dim3(NTOK / 2, NHEAD), 256, SMEM_ATTN>>>();

    // 3) out projection: out = (Yh+Yl) @ (Woh+Wol) + b_out
    gemm_tc<<<dim3(CIN / 64, NTOK / 64), 256>>>(
        (const __half*)pyh, (const __half*)pyl,
        (const __half*)pwoh, (const __half*)pwol,
        b_out, out, nullptr, NTOK, CIN, CIN);
}

// round 16
// speedup vs baseline: 1.1845x; 1.0048x over previous
#include <cuda_runtime.h>
#include <cuda_fp16.h>
#include <cstdint>

// Problem constants
#define NTOK   256
#define DH     64
#define NHEAD  8
#define CIN    512
#define NPROJ  2560   // 5*CIN

// Scratch (device globals: no allocation allowed)
__device__ __align__(16) __half g_Ph[NTOK * NPROJ];     // projection, half
__device__ __align__(16) __half g_xh[NTOK * CIN],  g_xl[NTOK * CIN];
__device__ __align__(16) __half g_wah[CIN * NPROJ], g_wal[CIN * NPROJ];
__device__ __align__(16) __half g_woh[CIN * CIN],  g_wol[CIN * CIN];
__device__ __align__(16) __half g_yh[NTOK * CIN],  g_yl[NTOK * CIN];

// ---------------- PTX helpers ----------------
__device__ __forceinline__ uint32_t smem_u32(const void* p) {
    uint32_t r;
    asm("{ .reg .u64 t; cvta.to.shared.u64 t, %1; cvt.u32.u64 %0, t; }"
        : "=r"(r) : "l"(p));
    return r;
}
__device__ __forceinline__ void ldsm_x4(uint32_t* r, uint32_t addr) {
    asm volatile("ldmatrix.sync.aligned.m8n8.x4.shared.b16 {%0,%1,%2,%3}, [%4];"
                 : "=r"(r[0]), "=r"(r[1]), "=r"(r[2]), "=r"(r[3]) : "r"(addr));
}
__device__ __forceinline__ void ldsm_x4_t(uint32_t* r, uint32_t addr) {
    asm volatile("ldmatrix.sync.aligned.m8n8.x4.trans.shared.b16 {%0,%1,%2,%3}, [%4];"
                 : "=r"(r[0]), "=r"(r[1]), "=r"(r[2]), "=r"(r[3]) : "r"(addr));
}
// fp32-accumulator mma (PV, lsum, GEMMs)
__device__ __forceinline__ void mma_f16(float* d, const uint32_t* a, uint32_t b0, uint32_t b1) {
    asm volatile(
        "mma.sync.aligned.m16n8k16.row.col.f32.f16.f16.f32 "
        "{%0,%1,%2,%3}, {%4,%5,%6,%7}, {%8,%9}, {%0,%1,%2,%3};"
        : "+f"(d[0]), "+f"(d[1]), "+f"(d[2]), "+f"(d[3])
        : "r"(a[0]), "r"(a[1]), "r"(a[2]), "r"(a[3]), "r"(b0), "r"(b1));
}
// fp16-accumulator mma (scores): D regs are packed half2 {c0,c1},{c2,c3}
__device__ __forceinline__ void mma_f16acc(uint32_t* d, const uint32_t* a, uint32_t b0, uint32_t b1) {
    asm volatile(
        "mma.sync.aligned.m16n8k16.row.col.f16.f16.f16.f16 "
        "{%0,%1}, {%2,%3,%4,%5}, {%6,%7}, {%0,%1};"
        : "+r"(d[0]), "+r"(d[1])
        : "r"(a[0]), "r"(a[1]), "r"(a[2]), "r"(a[3]), "r"(b0), "r"(b1));
}
__device__ __forceinline__ uint32_t ex2_f16x2(uint32_t a) {
    uint32_t d;
    asm("ex2.approx.f16x2 %0, %1;" : "=r"(d) : "r"(a));
    return d;
}
__device__ __forceinline__ uint32_t hmul2u(uint32_t a, uint32_t b) {
    uint32_t d;
    asm("mul.f16x2 %0, %1, %2;" : "=r"(d) : "r"(a), "r"(b));
    return d;
}

// ---------- fp32 -> (hi, lo) half split of x, W_att, W_out ----------
__global__ __launch_bounds__(256) void cvt_split(
    const float* __restrict__ x, const float* __restrict__ wa,
    const float* __restrict__ wo)
{
    const int NX = NTOK * CIN / 4, NA = CIN * NPROJ / 4, NO = CIN * CIN / 4;
    int idx = blockIdx.x * 256 + threadIdx.x;
    const float4* src; __half2* hi; __half2* lo;
    if (idx < NX)            { src = (const float4*)x;  hi = (__half2*)g_xh;  lo = (__half2*)g_xl; }
    else if (idx < NX + NA)  { idx -= NX;      src = (const float4*)wa; hi = (__half2*)g_wah; lo = (__half2*)g_wal; }
    else if (idx < NX+NA+NO) { idx -= NX + NA; src = (const float4*)wo; hi = (__half2*)g_woh; lo = (__half2*)g_wol; }
    else return;
    float4 v = src[idx];
    __half h0 = __float2half_rn(v.x), h1 = __float2half_rn(v.y);
    __half h2 = __float2half_rn(v.z), h3 = __float2half_rn(v.w);
    hi[idx * 2]     = __halves2half2(h0, h1);
    hi[idx * 2 + 1] = __halves2half2(h2, h3);
    lo[idx * 2]     = __halves2half2(__float2half_rn(v.x - __half2float(h0)),
                                     __float2half_rn(v.y - __half2float(h1)));
    lo[idx * 2 + 1] = __halves2half2(__float2half_rn(v.z - __half2float(h2)),
                                     __float2half_rn(v.w - __half2float(h3)));
}

// ---------- tensor-core GEMM, fp16 hi/lo split, 2-stage gmem pipeline ----------
__global__ __launch_bounds__(256) void gemm_tc(
    const __half* __restrict__ Ah, const __half* __restrict__ Al,
    const __half* __restrict__ Bh, const __half* __restrict__ Bl,
    const float* __restrict__ bias, float* __restrict__ C,
    __half* __restrict__ Ch, int M, int N, int K)
{
    __shared__ __half sA[2][64 * 64];
    __shared__ __half sB[2][64 * 64];
    const int t = threadIdx.x, w = t >> 5, lane = t & 31;
    const int wm = w >> 1, wn = w & 1;
    const int m0 = blockIdx.y * 64, n0 = blockIdx.x * 64;
    const int T = lane >> 3, rr = lane & 7;

    float acc[4][4];
#pragma unroll
    for (int nt = 0; nt < 4; ++nt)
#pragma unroll
        for (int r = 0; r < 4; ++r) acc[nt][r] = 0.f;

    const int arow = wm * 16 + (T & 1) * 8 + rr;
    const int asw = arow & 7;
    const int brow = (T & 1) * 8 + rr;

    uint4 pAh[2], pAl[2], pBh[2], pBl[2];
#pragma unroll
    for (int l = 0; l < 2; ++l) {
        int idx = l * 256 + t, row = idx >> 3, c = idx & 7;
        size_t aoff = (size_t)(m0 + row) * K + c * 8;
        pAh[l] = *(const uint4*)(Ah + aoff);
        pAl[l] = *(const uint4*)(Al + aoff);
        size_t boff = (size_t)row * N + n0 + c * 8;
        pBh[l] = *(const uint4*)(Bh + boff);
        pBl[l] = *(const uint4*)(Bl + boff);
    }

    for (int k0 = 0; k0 < K; k0 += 64) {
#pragma unroll
        for (int l = 0; l < 2; ++l) {
            int idx = l * 256 + t, row = idx >> 3, c = idx & 7, sw = c ^ (row & 7);
            ((uint4*)sA[0])[row * 8 + sw] = pAh[l];
            ((uint4*)sA[1])[row * 8 + sw] = pAl[l];
            ((uint4*)sB[0])[row * 8 + sw] = pBh[l];
            ((uint4*)sB[1])[row * 8 + sw] = pBl[l];
        }
        __syncthreads();

        if (k0 + 64 < K) {
#pragma unroll
            for (int l = 0; l < 2; ++l) {
                int idx = l * 256 + t, row = idx >> 3, c = idx & 7;
                size_t aoff = (size_t)(m0 + row) * K + (k0 + 64) + c * 8;
                pAh[l] = *(const uint4*)(Ah + aoff);
                pAl[l] = *(const uint4*)(Al + aoff);
                size_t boff = (size_t)(k0 + 64 + row) * N + n0 + c * 8;
                pBh[l] = *(const uint4*)(Bh + boff);
                pBl[l] = *(const uint4*)(Bl + boff);
            }
        }

        const uint32_t sAh_b = smem_u32(sA[0]), sAl_b = smem_u32(sA[1]);
        const uint32_t sBh_b = smem_u32(sB[0]), sBl_b = smem_u32(sB[1]);
        uint32_t ah[4][4], al[4][4], bh[4][2][4], bl[4][2][4];
#pragma unroll
        for (int kt = 0; kt < 4; ++kt) {
            uint32_t ach = (uint32_t)(arow * 128 + (((kt * 2 + (T >> 1)) ^ asw) * 16));
            ldsm_x4(ah[kt], sAh_b + ach);
            ldsm_x4(al[kt], sAl_b + ach);
            uint32_t rb = (uint32_t)((kt * 16 + brow) * 128);
#pragma unroll
            for (int np = 0; np < 2; ++np) {
                uint32_t bch = (uint32_t)(((wn * 4 + np * 2 + (T >> 1)) ^ rr) * 16);
                ldsm_x4_t(bh[kt][np], sBh_b + rb + bch);
                ldsm_x4_t(bl[kt][np], sBl_b + rb + bch);
            }
        }
#pragma unroll
        for (int kt = 0; kt < 4; ++kt)
#pragma unroll
            for (int np = 0; np < 2; ++np)
#pragma unroll
                for (int sub = 0; sub < 2; ++sub) {
                    int nt = np * 2 + sub;
                    uint32_t b0h = bh[kt][np][sub * 2], b1h = bh[kt][np][sub * 2 + 1];
                    uint32_t b0l = bl[kt][np][sub * 2], b1l = bl[kt][np][sub * 2 + 1];
                    mma_f16(acc[nt], ah[kt], b0h, b1h);
                    mma_f16(acc[nt], ah[kt], b0l, b1l);
                    mma_f16(acc[nt], al[kt], b0h, b1h);
                }
        __syncthreads();
    }

#pragma unroll
    for (int nt = 0; nt < 4; ++nt)
#pragma unroll
        for (int r = 0; r < 4; ++r) {
            int row = m0 + wm * 16 + (lane >> 2) + (r >> 1) * 8;
            int col = n0 + wn * 32 + nt * 8 + (lane & 3) * 2 + (r & 1);
            float v = acc[nt][r] + bias[col];
            if (C)  C[(size_t)row * N + col] = v;
            if (Ch) Ch[(size_t)row * N + col] = __float2half_rn(v);
        }
}

// ---------- third-order attention via tensor cores ----------
// One CTA per (query PAIR, head): 1024 CTAs, 256 threads (8 warps).
// Warps 0-3 handle query i0 (64 j-rows each: 4 m-tiles), warps 4-7 query i0+1.
// S-mma uses an fp16 accumulator: result regs are packed half2 in exactly the
// ex2/A-fragment layout, so exp is mma -> ex2.f16x2 -> mma with no F2FP repack.
// bb and vb live in separate buffers, both loaded at the top of each np so the
// vb LDS latency hides under the S mmas instead of trailing them (no WAR chain).
#define SMEM_ATTN 133408
#define ONES2 0x3C003C00u

__global__ __launch_bounds__(256, 1) void attn_mma()
{
    const int i0 = blockIdx.x * 2, h = blockIdx.y;
    const int t = threadIdx.x;
    const int w = t >> 5, lane = t & 31;
    const int qw = w >> 2;          // which query this warp serves
    const int ww = w & 3;           // warp index within query (owns 64 j-rows)

    extern __shared__ char smem[];
    __half* kjs = (__half*)(smem);
    __half* kks = (__half*)(smem + 32768);
    __half* vks = (__half*)(smem + 65536);
    __half* vjs = (__half*)(smem + 98304);
    __half* qsm = (__half*)(smem + 131072);          // [2][64]
    float*  ybuf = (float*)(smem + 131328);          // [8][64]
    float*  lbuf = (float*)(smem + 133376);          // [8]

    const int base = h * 5 * DH;

    // ---- stage tiles (each 2048 uint4; 8 per thread) ----
#pragma unroll
    for (int l = 0; l < 8; ++l) {
        int idx = l * 256 + t;
        int row = idx >> 3, c = idx & 7;
        int sw = c ^ (row & 7);
        const __half* src = g_Ph + row * NPROJ + base;
        ((uint4*)kjs)[row * 8 + sw] = ((const uint4*)(src + 1 * DH))[c];
        ((uint4*)kks)[row * 8 + sw] = ((const uint4*)(src + 2 * DH))[c];
        ((uint4*)vks)[row * 8 + sw] = ((const uint4*)(src + 4 * DH))[c];
        ((uint4*)vjs)[row * 8 + c]  = ((const uint4*)(src + 3 * DH))[c];
    }
    // scaled q for both queries (scale * log2(e) folded so exp -> ex2)
    if (t < 2 * DH) {
        int qi = t >> 6, d = t & 63;
        float qv = __half2float(g_Ph[(i0 + qi) * NPROJ + base + d]);
        qsm[t] = __float2half_rn(qv * 0.18033688011112042f);
    }
    __syncthreads();

    const int T = lane >> 3;
    const int rr = lane & 7;
    uint32_t chunkx[4];
#pragma unroll
    for (int c4 = 0; c4 < 4; ++c4)
        chunkx[c4] = (uint32_t)((((c4 * 2 + (T >> 1)) ^ rr) & 7) * 16);
    const uint32_t rowoff0 = (uint32_t)(((T & 1) * 8 + rr) * 128);
    const uint32_t kks_b = smem_u32(kks);
    const uint32_t vks_b = smem_u32(vks);
    const int kcol = (lane & 3) * 2;

    // ---- A-fragments: afr[mt] = ldsm(kj rows) * q-frag, 4 m-tiles ----
    uint32_t afr[4][4][4];
    {
        const uint32_t kjs_b = smem_u32(kjs);
#pragma unroll
        for (int mt = 0; mt < 4; ++mt) {
            uint32_t rbase = (uint32_t)((ww * 64 + mt * 16) * 128) + rowoff0;
#pragma unroll
            for (int kt = 0; kt < 4; ++kt) {
                ldsm_x4(afr[mt][kt], kjs_b + rbase + chunkx[kt]);
                uint32_t q0 = *(const uint32_t*)(qsm + qw * 64 + kt * 16 + kcol);
                uint32_t q8 = *(const uint32_t*)(qsm + qw * 64 + kt * 16 + 8 + kcol);
                afr[mt][kt][0] = hmul2u(afr[mt][kt][0], q0);
                afr[mt][kt][1] = hmul2u(afr[mt][kt][1], q0);
                afr[mt][kt][2] = hmul2u(afr[mt][kt][2], q8);
                afr[mt][kt][3] = hmul2u(afr[mt][kt][3], q8);
            }
        }
    }

    float macc[4][8][4];
#pragma unroll
    for (int mt = 0; mt < 4; ++mt)
#pragma unroll
        for (int dn = 0; dn < 8; ++dn)
#pragma unroll
            for (int r = 0; r < 4; ++r) macc[mt][dn][r] = 0.f;
    float lacc[4] = {0.f, 0.f, 0.f, 0.f};

#pragma unroll 1
    for (int np = 0; np < 16; ++np) {
        const uint32_t ro = rowoff0 + (uint32_t)(np * 2048);
        uint32_t bb[4][4], vb[4][4];
        // Load BOTH fragment sets up front: vb's latency hides under S mmas/ex2.
#pragma unroll
        for (int kt = 0; kt < 4; ++kt) ldsm_x4(bb[kt], kks_b + ro + chunkx[kt]);
#pragma unroll
        for (int dp = 0; dp < 4; ++dp) ldsm_x4_t(vb[dp], vks_b + ro + chunkx[dp]);

        // S = KJq @ KK^T (fp16 acc, packed half2) -> exp via ex2.f16x2, no repack
        uint32_t pa[4][4];
#pragma unroll
        for (int mt = 0; mt < 4; ++mt) {
            uint32_t s0[2] = {0u, 0u}, s1[2] = {0u, 0u};   // nt0, nt1 half2 accums
#pragma unroll
            for (int kt = 0; kt < 4; ++kt) {
                mma_f16acc(s0, afr[mt][kt], bb[kt][0], bb[kt][2]);
                mma_f16acc(s1, afr[mt][kt], bb[kt][1], bb[kt][3]);
            }
            pa[mt][0] = ex2_f16x2(s0[0]);
            pa[mt][1] = ex2_f16x2(s0[1]);
            pa[mt][2] = ex2_f16x2(s1[0]);
            pa[mt][3] = ex2_f16x2(s1[1]);
        }

        // M += P @ VK per m-tile; lsum via ones-column mma (fp32 acc)
#pragma unroll
        for (int mt = 0; mt < 4; ++mt) {
#pragma unroll
            for (int dn = 0; dn < 8; ++dn) {
                int dp = dn >> 1;
                if (dn & 1) mma_f16(macc[mt][dn], pa[mt], vb[dp][2], vb[dp][3]);
                else        mma_f16(macc[mt][dn], pa[mt], vb[dp][0], vb[dp][1]);
            }
            mma_f16(lacc, pa[mt], ONES2, ONES2);
        }
    }

    // ---- denominator (each row sum replicated across 8 lanes/cols) ----
    float lsum = lacc[0] + lacc[1] + lacc[2] + lacc[3];
#pragma unroll
    for (int o = 16; o > 0; o >>= 1) lsum += __shfl_xor_sync(0xffffffffu, lsum, o);
    if (lane == 0) lbuf[w] = lsum * 0.125f;

    // ---- y partials: sum_j vj[j,d] * M[j,d] over this warp's 64 rows ----
    float ps[8][2];
#pragma unroll
    for (int nt = 0; nt < 8; ++nt) { ps[nt][0] = 0.f; ps[nt][1] = 0.f; }
#pragma unroll
    for (int mt = 0; mt < 4; ++mt)
#pragma unroll
        for (int nt = 0; nt < 8; ++nt) {
            int d0 = nt * 8 + (lane & 3) * 2;
#pragma unroll
            for (int rg = 0; rg < 2; ++rg) {
                int j = ww * 64 + mt * 16 + (lane >> 2) + rg * 8;
                float2 vf = __half22float2(*(const __half2*)(vjs + j * 64 + d0));
                ps[nt][0] += macc[mt][nt][rg * 2]     * vf.x;
                ps[nt][1] += macc[mt][nt][rg * 2 + 1] * vf.y;
            }
        }
#pragma unroll
    for (int o = 4; o <= 16; o <<= 1)
#pragma unroll
        for (int nt = 0; nt < 8; ++nt) {
            ps[nt][0] += __shfl_xor_sync(0xffffffffu, ps[nt][0], o);
            ps[nt][1] += __shfl_xor_sync(0xffffffffu, ps[nt][1], o);
        }
    if (lane < 4) {
#pragma unroll
        for (int nt = 0; nt < 8; ++nt) {
            ybuf[w * 64 + nt * 8 + lane * 2]     = ps[nt][0];
            ybuf[w * 64 + nt * 8 + lane * 2 + 1] = ps[nt][1];
        }
    }
    __syncthreads();

    // ---- finalize both queries: threads [0,64) -> q0, [64,128) -> q1 ----
    if (t < 2 * DH) {
        int qi = t >> 6, d = t & 63;
        float acc2 = 0.f, lt = 0.f;
#pragma unroll
        for (int ww2 = 0; ww2 < 4; ++ww2) {
            acc2 += ybuf[(qi * 4 + ww2) * 64 + d];
            lt   += lbuf[qi * 4 + ww2];
        }
        float y = acc2 / lt;
        __half hy = __float2half_rn(y);
        g_yh[(i0 + qi) * CIN + h * DH + d] = hy;
        g_yl[(i0 + qi) * CIN + h * DH + d] = __float2half_rn(y - __half2float(hy));
    }
}

// ---------------------------------------------------------------------------
extern "C" void kernel_launch(void* const* d_in, const int* in_sizes, int n_in,
                              void* d_out, int out_size)
{
    const float* x     = (const float*)d_in[0];
    const float* W_att = (const float*)d_in[1];
    const float* b_att = (const float*)d_in[2];
    const float* W_out = (const float*)d_in[3];
    const float* b_out = (const float*)d_in[4];
    float* out = (float*)d_out;

    void *pxh, *pxl, *pwah, *pwal, *pwoh, *pwol, *pPh, *pyh, *pyl;
    cudaGetSymbolAddress(&pxh, g_xh);   cudaGetSymbolAddress(&pxl, g_xl);
    cudaGetSymbolAddress(&pwah, g_wah); cudaGetSymbolAddress(&pwal, g_wal);
    cudaGetSymbolAddress(&pwoh, g_woh); cudaGetSymbolAddress(&pwol, g_wol);
    cudaGetSymbolAddress(&pPh, g_Ph);
    cudaGetSymbolAddress(&pyh, g_yh);   cudaGetSymbolAddress(&pyl, g_yl);

    // 0) split-convert inputs to (hi, lo) halves
    const int n4 = (NTOK * CIN + CIN * NPROJ + CIN * CIN) / 4;
    cvt_split<<<(n4 + 255) / 256, 256>>>(x, W_att, W_out);

    // 1) projection: g_Ph = half(x @ W_att + b_att), fp32-quality via 3-mma split
    gemm_tc<<<dim3(NPROJ / 64, NTOK / 64), 256>>>(
        (const __half*)pxh, (const __half*)pxl,
        (const __half*)pwah, (const __half*)pwal,
        b_att, nullptr, (__half*)pPh, NTOK, NPROJ, CIN);

    // 2) third-order attention (8 warps, query pair per CTA, f16-acc scores)
    cudaFuncSetAttribute(attn_mma, cudaFuncAttributeMaxDynamicSharedMemorySize, SMEM_ATTN);
    attn_mma<<<dim3(NTOK / 2, NHEAD), 256, SMEM_ATTN>>>();

    // 3) out projection: out = (Yh+Yl) @ (Woh+Wol) + b_out
    gemm_tc<<<dim3(CIN / 64, NTOK / 64), 256>>>(
        (const __half*)pyh, (const __half*)pyl,
        (const __half*)pwoh, (const __half*)pwol,
        b_out, out, nullptr, NTOK, CIN, CIN);
}

// round 17
// speedup vs baseline: 1.1989x; 1.0122x over previous
#include <cuda_runtime.h>
#include <cuda_fp16.h>
#include <cstdint>

// Problem constants
#define NTOK   256
#define DH     64
#define NHEAD  8
#define CIN    512
#define NPROJ  2560   // 5*CIN

// Scratch (device globals: no allocation allowed)
__device__ __align__(16) __half g_Ph[NTOK * NPROJ];     // projection, half
__device__ __align__(16) __half g_xh[NTOK * CIN],  g_xl[NTOK * CIN];
__device__ __align__(16) __half g_wah[CIN * NPROJ], g_wal[CIN * NPROJ];
__device__ __align__(16) __half g_woh[CIN * CIN],  g_wol[CIN * CIN];
__device__ __align__(16) __half g_yh[NTOK * CIN],  g_yl[NTOK * CIN];

// ---------------- PTX helpers ----------------
__device__ __forceinline__ uint32_t smem_u32(const void* p) {
    uint32_t r;
    asm("{ .reg .u64 t; cvta.to.shared.u64 t, %1; cvt.u32.u64 %0, t; }"
        : "=r"(r) : "l"(p));
    return r;
}
__device__ __forceinline__ void ldsm_x4(uint32_t* r, uint32_t addr) {
    asm volatile("ldmatrix.sync.aligned.m8n8.x4.shared.b16 {%0,%1,%2,%3}, [%4];"
                 : "=r"(r[0]), "=r"(r[1]), "=r"(r[2]), "=r"(r[3]) : "r"(addr));
}
__device__ __forceinline__ void ldsm_x4_t(uint32_t* r, uint32_t addr) {
    asm volatile("ldmatrix.sync.aligned.m8n8.x4.trans.shared.b16 {%0,%1,%2,%3}, [%4];"
                 : "=r"(r[0]), "=r"(r[1]), "=r"(r[2]), "=r"(r[3]) : "r"(addr));
}
// fp32-accumulator mma (PV, lsum, GEMMs)
__device__ __forceinline__ void mma_f16(float* d, const uint32_t* a, uint32_t b0, uint32_t b1) {
    asm volatile(
        "mma.sync.aligned.m16n8k16.row.col.f32.f16.f16.f32 "
        "{%0,%1,%2,%3}, {%4,%5,%6,%7}, {%8,%9}, {%0,%1,%2,%3};"
        : "+f"(d[0]), "+f"(d[1]), "+f"(d[2]), "+f"(d[3])
        : "r"(a[0]), "r"(a[1]), "r"(a[2]), "r"(a[3]), "r"(b0), "r"(b1));
}
// fp16-accumulator mma (scores): D regs are packed half2 {c0,c1},{c2,c3}
__device__ __forceinline__ void mma_f16acc(uint32_t* d, const uint32_t* a, uint32_t b0, uint32_t b1) {
    asm volatile(
        "mma.sync.aligned.m16n8k16.row.col.f16.f16.f16.f16 "
        "{%0,%1}, {%2,%3,%4,%5}, {%6,%7}, {%0,%1};"
        : "+r"(d[0]), "+r"(d[1])
        : "r"(a[0]), "r"(a[1]), "r"(a[2]), "r"(a[3]), "r"(b0), "r"(b1));
}
__device__ __forceinline__ uint32_t ex2_f16x2(uint32_t a) {
    uint32_t d;
    asm("ex2.approx.f16x2 %0, %1;" : "=r"(d) : "r"(a));
    return d;
}
__device__ __forceinline__ uint32_t hmul2u(uint32_t a, uint32_t b) {
    uint32_t d;
    asm("mul.f16x2 %0, %1, %2;" : "=r"(d) : "r"(a), "r"(b));
    return d;
}

// ---------- fp32 -> (hi, lo) half split of x, W_att, W_out ----------
__global__ __launch_bounds__(256) void cvt_split(
    const float* __restrict__ x, const float* __restrict__ wa,
    const float* __restrict__ wo)
{
    const int NX = NTOK * CIN / 4, NA = CIN * NPROJ / 4, NO = CIN * CIN / 4;
    int idx = blockIdx.x * 256 + threadIdx.x;
    const float4* src; __half2* hi; __half2* lo;
    if (idx < NX)            { src = (const float4*)x;  hi = (__half2*)g_xh;  lo = (__half2*)g_xl; }
    else if (idx < NX + NA)  { idx -= NX;      src = (const float4*)wa; hi = (__half2*)g_wah; lo = (__half2*)g_wal; }
    else if (idx < NX+NA+NO) { idx -= NX + NA; src = (const float4*)wo; hi = (__half2*)g_woh; lo = (__half2*)g_wol; }
    else return;
    float4 v = src[idx];
    __half h0 = __float2half_rn(v.x), h1 = __float2half_rn(v.y);
    __half h2 = __float2half_rn(v.z), h3 = __float2half_rn(v.w);
    hi[idx * 2]     = __halves2half2(h0, h1);
    hi[idx * 2 + 1] = __halves2half2(h2, h3);
    lo[idx * 2]     = __halves2half2(__float2half_rn(v.x - __half2float(h0)),
                                     __float2half_rn(v.y - __half2float(h1)));
    lo[idx * 2 + 1] = __halves2half2(__float2half_rn(v.z - __half2float(h2)),
                                     __float2half_rn(v.w - __half2float(h3)));
}

// ---------- tensor-core GEMM, fp16 hi/lo split, 2-stage gmem pipeline ----------
__global__ __launch_bounds__(256) void gemm_tc(
    const __half* __restrict__ Ah, const __half* __restrict__ Al,
    const __half* __restrict__ Bh, const __half* __restrict__ Bl,
    const float* __restrict__ bias, float* __restrict__ C,
    __half* __restrict__ Ch, int M, int N, int K)
{
    __shared__ __half sA[2][64 * 64];
    __shared__ __half sB[2][64 * 64];
    const int t = threadIdx.x, w = t >> 5, lane = t & 31;
    const int wm = w >> 1, wn = w & 1;
    const int m0 = blockIdx.y * 64, n0 = blockIdx.x * 64;
    const int T = lane >> 3, rr = lane & 7;

    float acc[4][4];
#pragma unroll
    for (int nt = 0; nt < 4; ++nt)
#pragma unroll
        for (int r = 0; r < 4; ++r) acc[nt][r] = 0.f;

    const int arow = wm * 16 + (T & 1) * 8 + rr;
    const int asw = arow & 7;
    const int brow = (T & 1) * 8 + rr;

    uint4 pAh[2], pAl[2], pBh[2], pBl[2];
#pragma unroll
    for (int l = 0; l < 2; ++l) {
        int idx = l * 256 + t, row = idx >> 3, c = idx & 7;
        size_t aoff = (size_t)(m0 + row) * K + c * 8;
        pAh[l] = *(const uint4*)(Ah + aoff);
        pAl[l] = *(const uint4*)(Al + aoff);
        size_t boff = (size_t)row * N + n0 + c * 8;
        pBh[l] = *(const uint4*)(Bh + boff);
        pBl[l] = *(const uint4*)(Bl + boff);
    }

    for (int k0 = 0; k0 < K; k0 += 64) {
#pragma unroll
        for (int l = 0; l < 2; ++l) {
            int idx = l * 256 + t, row = idx >> 3, c = idx & 7, sw = c ^ (row & 7);
            ((uint4*)sA[0])[row * 8 + sw] = pAh[l];
            ((uint4*)sA[1])[row * 8 + sw] = pAl[l];
            ((uint4*)sB[0])[row * 8 + sw] = pBh[l];
            ((uint4*)sB[1])[row * 8 + sw] = pBl[l];
        }
        __syncthreads();

        if (k0 + 64 < K) {
#pragma unroll
            for (int l = 0; l < 2; ++l) {
                int idx = l * 256 + t, row = idx >> 3, c = idx & 7;
                size_t aoff = (size_t)(m0 + row) * K + (k0 + 64) + c * 8;
                pAh[l] = *(const uint4*)(Ah + aoff);
                pAl[l] = *(const uint4*)(Al + aoff);
                size_t boff = (size_t)(k0 + 64 + row) * N + n0 + c * 8;
                pBh[l] = *(const uint4*)(Bh + boff);
                pBl[l] = *(const uint4*)(Bl + boff);
            }
        }

        const uint32_t sAh_b = smem_u32(sA[0]), sAl_b = smem_u32(sA[1]);
        const uint32_t sBh_b = smem_u32(sB[0]), sBl_b = smem_u32(sB[1]);
        uint32_t ah[4][4], al[4][4], bh[4][2][4], bl[4][2][4];
#pragma unroll
        for (int kt = 0; kt < 4; ++kt) {
            uint32_t ach = (uint32_t)(arow * 128 + (((kt * 2 + (T >> 1)) ^ asw) * 16));
            ldsm_x4(ah[kt], sAh_b + ach);
            ldsm_x4(al[kt], sAl_b + ach);
            uint32_t rb = (uint32_t)((kt * 16 + brow) * 128);
#pragma unroll
            for (int np = 0; np < 2; ++np) {
                uint32_t bch = (uint32_t)(((wn * 4 + np * 2 + (T >> 1)) ^ rr) * 16);
                ldsm_x4_t(bh[kt][np], sBh_b + rb + bch);
                ldsm_x4_t(bl[kt][np], sBl_b + rb + bch);
            }
        }
#pragma unroll
        for (int kt = 0; kt < 4; ++kt)
#pragma unroll
            for (int np = 0; np < 2; ++np)
#pragma unroll
                for (int sub = 0; sub < 2; ++sub) {
                    int nt = np * 2 + sub;
                    uint32_t b0h = bh[kt][np][sub * 2], b1h = bh[kt][np][sub * 2 + 1];
                    uint32_t b0l = bl[kt][np][sub * 2], b1l = bl[kt][np][sub * 2 + 1];
                    mma_f16(acc[nt], ah[kt], b0h, b1h);
                    mma_f16(acc[nt], ah[kt], b0l, b1l);
                    mma_f16(acc[nt], al[kt], b0h, b1h);
                }
        __syncthreads();
    }

#pragma unroll
    for (int nt = 0; nt < 4; ++nt)
#pragma unroll
        for (int r = 0; r < 4; ++r) {
            int row = m0 + wm * 16 + (lane >> 2) + (r >> 1) * 8;
            int col = n0 + wn * 32 + nt * 8 + (lane & 3) * 2 + (r & 1);
            float v = acc[nt][r] + bias[col];
            if (C)  C[(size_t)row * N + col] = v;
            if (Ch) Ch[(size_t)row * N + col] = __float2half_rn(v);
        }
}

// ---------- third-order attention via tensor cores ----------
// One CTA per (query PAIR, head): 1024 CTAs, 256 threads (8 warps).
// Warps 0-3 handle query i0 (64 j-rows each: 4 m-tiles), warps 4-7 query i0+1.
// S-mma uses an fp16 accumulator: result regs are packed half2 in exactly the
// ex2/A-fragment layout, so exp is mma -> ex2.f16x2 -> mma with no F2FP repack.
// bb and vb live in separate buffers, both loaded at the top of each np so the
// vb LDS latency hides under the S mmas instead of trailing them (no WAR chain).
#define SMEM_ATTN 133408
#define ONES2 0x3C003C00u

__global__ __launch_bounds__(256, 1) void attn_mma()
{
    const int i0 = blockIdx.x * 2, h = blockIdx.y;
    const int t = threadIdx.x;
    const int w = t >> 5, lane = t & 31;
    const int qw = w >> 2;          // which query this warp serves
    const int ww = w & 3;           // warp index within query (owns 64 j-rows)

    extern __shared__ char smem[];
    __half* kjs = (__half*)(smem);
    __half* kks = (__half*)(smem + 32768);
    __half* vks = (__half*)(smem + 65536);
    __half* vjs = (__half*)(smem + 98304);
    __half* qsm = (__half*)(smem + 131072);          // [2][64]
    float*  ybuf = (float*)(smem + 131328);          // [8][64]
    float*  lbuf = (float*)(smem + 133376);          // [8]

    const int base = h * 5 * DH;

    // ---- stage tiles (each 2048 uint4; 8 per thread) ----
#pragma unroll
    for (int l = 0; l < 8; ++l) {
        int idx = l * 256 + t;
        int row = idx >> 3, c = idx & 7;
        int sw = c ^ (row & 7);
        const __half* src = g_Ph + row * NPROJ + base;
        ((uint4*)kjs)[row * 8 + sw] = ((const uint4*)(src + 1 * DH))[c];
        ((uint4*)kks)[row * 8 + sw] = ((const uint4*)(src + 2 * DH))[c];
        ((uint4*)vks)[row * 8 + sw] = ((const uint4*)(src + 4 * DH))[c];
        ((uint4*)vjs)[row * 8 + c]  = ((const uint4*)(src + 3 * DH))[c];
    }
    // scaled q for both queries (scale * log2(e) folded so exp -> ex2)
    if (t < 2 * DH) {
        int qi = t >> 6, d = t & 63;
        float qv = __half2float(g_Ph[(i0 + qi) * NPROJ + base + d]);
        qsm[t] = __float2half_rn(qv * 0.18033688011112042f);
    }
    __syncthreads();

    const int T = lane >> 3;
    const int rr = lane & 7;
    uint32_t chunkx[4];
#pragma unroll
    for (int c4 = 0; c4 < 4; ++c4)
        chunkx[c4] = (uint32_t)((((c4 * 2 + (T >> 1)) ^ rr) & 7) * 16);
    const uint32_t rowoff0 = (uint32_t)(((T & 1) * 8 + rr) * 128);
    const uint32_t kks_b = smem_u32(kks);
    const uint32_t vks_b = smem_u32(vks);
    const int kcol = (lane & 3) * 2;

    // ---- A-fragments: afr[mt] = ldsm(kj rows) * q-frag, 4 m-tiles ----
    uint32_t afr[4][4][4];
    {
        const uint32_t kjs_b = smem_u32(kjs);
#pragma unroll
        for (int mt = 0; mt < 4; ++mt) {
            uint32_t rbase = (uint32_t)((ww * 64 + mt * 16) * 128) + rowoff0;
#pragma unroll
            for (int kt = 0; kt < 4; ++kt) {
                ldsm_x4(afr[mt][kt], kjs_b + rbase + chunkx[kt]);
                uint32_t q0 = *(const uint32_t*)(qsm + qw * 64 + kt * 16 + kcol);
                uint32_t q8 = *(const uint32_t*)(qsm + qw * 64 + kt * 16 + 8 + kcol);
                afr[mt][kt][0] = hmul2u(afr[mt][kt][0], q0);
                afr[mt][kt][1] = hmul2u(afr[mt][kt][1], q0);
                afr[mt][kt][2] = hmul2u(afr[mt][kt][2], q8);
                afr[mt][kt][3] = hmul2u(afr[mt][kt][3], q8);
            }
        }
    }

    float macc[4][8][4];
#pragma unroll
    for (int mt = 0; mt < 4; ++mt)
#pragma unroll
        for (int dn = 0; dn < 8; ++dn)
#pragma unroll
            for (int r = 0; r < 4; ++r) macc[mt][dn][r] = 0.f;
    float lacc[4] = {0.f, 0.f, 0.f, 0.f};

#pragma unroll 1
    for (int np = 0; np < 16; ++np) {
        const uint32_t ro = rowoff0 + (uint32_t)(np * 2048);
        uint32_t bb[4][4], vb[4][4];
        // Load BOTH fragment sets up front: vb's latency hides under S mmas/ex2.
#pragma unroll
        for (int kt = 0; kt < 4; ++kt) ldsm_x4(bb[kt], kks_b + ro + chunkx[kt]);
#pragma unroll
        for (int dp = 0; dp < 4; ++dp) ldsm_x4_t(vb[dp], vks_b + ro + chunkx[dp]);

        // S = KJq @ KK^T (fp16 acc, packed half2) -> exp via ex2.f16x2, no repack
        uint32_t pa[4][4];
#pragma unroll
        for (int mt = 0; mt < 4; ++mt) {
            uint32_t s0[2] = {0u, 0u}, s1[2] = {0u, 0u};   // nt0, nt1 half2 accums
#pragma unroll
            for (int kt = 0; kt < 4; ++kt) {
                mma_f16acc(s0, afr[mt][kt], bb[kt][0], bb[kt][2]);
                mma_f16acc(s1, afr[mt][kt], bb[kt][1], bb[kt][3]);
            }
            pa[mt][0] = ex2_f16x2(s0[0]);
            pa[mt][1] = ex2_f16x2(s0[1]);
            pa[mt][2] = ex2_f16x2(s1[0]);
            pa[mt][3] = ex2_f16x2(s1[1]);
        }

        // M += P @ VK per m-tile; lsum via ones-column mma (fp32 acc)
#pragma unroll
        for (int mt = 0; mt < 4; ++mt) {
#pragma unroll
            for (int dn = 0; dn < 8; ++dn) {
                int dp = dn >> 1;
                if (dn & 1) mma_f16(macc[mt][dn], pa[mt], vb[dp][2], vb[dp][3]);
                else        mma_f16(macc[mt][dn], pa[mt], vb[dp][0], vb[dp][1]);
            }
            mma_f16(lacc, pa[mt], ONES2, ONES2);
        }
    }

    // ---- denominator (each row sum replicated across 8 lanes/cols) ----
    float lsum = lacc[0] + lacc[1] + lacc[2] + lacc[3];
#pragma unroll
    for (int o = 16; o > 0; o >>= 1) lsum += __shfl_xor_sync(0xffffffffu, lsum, o);
    if (lane == 0) lbuf[w] = lsum * 0.125f;

    // ---- y partials: sum_j vj[j,d] * M[j,d] over this warp's 64 rows ----
    float ps[8][2];
#pragma unroll
    for (int nt = 0; nt < 8; ++nt) { ps[nt][0] = 0.f; ps[nt][1] = 0.f; }
#pragma unroll
    for (int mt = 0; mt < 4; ++mt)
#pragma unroll
        for (int nt = 0; nt < 8; ++nt) {
            int d0 = nt * 8 + (lane & 3) * 2;
#pragma unroll
            for (int rg = 0; rg < 2; ++rg) {
                int j = ww * 64 + mt * 16 + (lane >> 2) + rg * 8;
                float2 vf = __half22float2(*(const __half2*)(vjs + j * 64 + d0));
                ps[nt][0] += macc[mt][nt][rg * 2]     * vf.x;
                ps[nt][1] += macc[mt][nt][rg * 2 + 1] * vf.y;
            }
        }
#pragma unroll
    for (int o = 4; o <= 16; o <<= 1)
#pragma unroll
        for (int nt = 0; nt < 8; ++nt) {
            ps[nt][0] += __shfl_xor_sync(0xffffffffu, ps[nt][0], o);
            ps[nt][1] += __shfl_xor_sync(0xffffffffu, ps[nt][1], o);
        }
    if (lane < 4) {
#pragma unroll
        for (int nt = 0; nt < 8; ++nt) {
            ybuf[w * 64 + nt * 8 + lane * 2]     = ps[nt][0];
            ybuf[w * 64 + nt * 8 + lane * 2 + 1] = ps[nt][1];
        }
    }
    __syncthreads();

    // ---- finalize both queries: threads [0,64) -> q0, [64,128) -> q1 ----
    if (t < 2 * DH) {
        int qi = t >> 6, d = t & 63;
        float acc2 = 0.f, lt = 0.f;
#pragma unroll
        for (int ww2 = 0; ww2 < 4; ++ww2) {
            acc2 += ybuf[(qi * 4 + ww2) * 64 + d];
            lt   += lbuf[qi * 4 + ww2];
        }
        float y = acc2 / lt;
        __half hy = __float2half_rn(y);
        g_yh[(i0 + qi) * CIN + h * DH + d] = hy;
        g_yl[(i0 + qi) * CIN + h * DH + d] = __float2half_rn(y - __half2float(hy));
    }
}

// ---------------------------------------------------------------------------
extern "C" void kernel_launch(void* const* d_in, const int* in_sizes, int n_in,
                              void* d_out, int out_size)
{
    const float* x     = (const float*)d_in[0];
    const float* W_att = (const float*)d_in[1];
    const float* b_att = (const float*)d_in[2];
    const float* W_out = (const float*)d_in[3];
    const float* b_out = (const float*)d_in[4];
    float* out = (float*)d_out;

    void *pxh, *pxl, *pwah, *pwal, *pwoh, *pwol, *pPh, *pyh, *pyl;
    cudaGetSymbolAddress(&pxh, g_xh);   cudaGetSymbolAddress(&pxl, g_xl);
    cudaGetSymbolAddress(&pwah, g_wah); cudaGetSymbolAddress(&pwal, g_wal);
    cudaGetSymbolAddress(&pwoh, g_woh); cudaGetSymbolAddress(&pwol, g_wol);
    cudaGetSymbolAddress(&pPh, g_Ph);
    cudaGetSymbolAddress(&pyh, g_yh);   cudaGetSymbolAddress(&pyl, g_yl);

    // 0) split-convert inputs to (hi, lo) halves
    const int n4 = (NTOK * CIN + CIN * NPROJ + CIN * CIN) / 4;
    cvt_split<<<(n4 + 255) / 256, 256>>>(x, W_att, W_out);

    // 1) projection: g_Ph = half(x @ W_att + b_att), fp32-quality via 3-mma split
    gemm_tc<<<dim3(NPROJ / 64, NTOK / 64), 256>>>(
        (const __half*)pxh, (const __half*)pxl,
        (const __half*)pwah, (const __half*)pwal,
        b_att, nullptr, (__half*)pPh, NTOK, NPROJ, CIN);

    // 2) third-order attention (8 warps, query pair per CTA, f16-acc scores)
    cudaFuncSetAttribute(attn_mma, cudaFuncAttributeMaxDynamicSharedMemorySize, SMEM_ATTN);
    attn_mma<<<dim3(NTOK / 2, NHEAD), 256, SMEM_ATTN>>>();

    // 3) out projection: out = (Yh+Yl) @ (Woh+Wol) + b_out
    gemm_tc<<<dim3(CIN / 64, NTOK / 64), 256>>>(
        (const __half*)pyh, (const __half*)pyl,
        (const __half*)pwoh, (const __half*)pwol,
        b_out, out, nullptr, NTOK, CIN, CIN);
}